// round 11
// baseline (speedup 1.0000x reference)
#include <cuda_runtime.h>
#include <cuda_fp16.h>
#include <cuda_bf16.h>
#include <math.h>
#include <stdint.h>

#define BATCH 32
#define EPS 1e-5f

__device__ __forceinline__ uint32_t f2tf(float f) {
    uint32_t r; asm("cvt.rna.tf32.f32 %0,%1;" : "=r"(r) : "f"(f)); return r;
}
__device__ __forceinline__ void mma8(float* c, uint32_t a0, uint32_t a1,
                                     uint32_t a2, uint32_t a3,
                                     uint32_t b0, uint32_t b1) {
    asm("mma.sync.aligned.m16n8k8.row.col.f32.tf32.tf32.f32 "
        "{%0,%1,%2,%3},{%4,%5,%6,%7},{%8,%9},{%0,%1,%2,%3};"
        : "+f"(c[0]), "+f"(c[1]), "+f"(c[2]), "+f"(c[3])
        : "r"(a0), "r"(a1), "r"(a2), "r"(a3), "r"(b0), "r"(b1));
}
__device__ __forceinline__ void mma16(float* c, uint32_t a0, uint32_t a1,
                                      uint32_t a2, uint32_t a3,
                                      uint32_t b0, uint32_t b1) {
    asm("mma.sync.aligned.m16n8k16.row.col.f32.f16.f16.f32 "
        "{%0,%1,%2,%3},{%4,%5,%6,%7},{%8,%9},{%0,%1,%2,%3};"
        : "+f"(c[0]), "+f"(c[1]), "+f"(c[2]), "+f"(c[3])
        : "r"(a0), "r"(a1), "r"(a2), "r"(a3), "r"(b0), "r"(b1));
}
__device__ __forceinline__ uint32_t s2u(const void* p) {
    return (uint32_t)__cvta_generic_to_shared(p);
}
__device__ __forceinline__ void ldsm4(uint32_t& r0, uint32_t& r1,
                                      uint32_t& r2, uint32_t& r3, uint32_t a) {
    asm volatile("ldmatrix.sync.aligned.m8n8.x4.shared.b16 {%0,%1,%2,%3},[%4];"
        : "=r"(r0), "=r"(r1), "=r"(r2), "=r"(r3) : "r"(a));
}

// ---------------- scratch ----------------
__device__ __align__(256) __half g_buf1h[BATCH*160*160*32];  // NHWC
__device__ __align__(256) __half g_buf2h[BATCH*80*80*32];    // NHWC
__device__ __align__(256) __half g_buf3h[BATCH*73*73*16];    // NHWC
__device__ float g_buf4[BATCH*16*66*66];                     // NCHW
__device__ float g_buf5[BATCH*16*31*31];
__device__ float g_buf6[BATCH*16*27*27];
__device__ float g_part[24*32*4096];
__device__ float g_fc1[BATCH*4096];
__device__ float g_fc2[BATCH*2048];

// =====================================================================
// conv1 (fp16 mma + ldmatrix): x NCHW fp32 -> g_buf1h NHWC half
// =====================================================================
#define C1_KP 536
#define C1_XSH 4432
__global__ void __launch_bounds__(256) conv1_h(
    const float* __restrict__ x, const float* __restrict__ w,
    const float* __restrict__ bias, __half* __restrict__ out)
{
    extern __shared__ __half smh[];
    __half* xs0 = smh;
    __half* xs1 = smh + C1_XSH;
    __half* ws  = smh + 2*C1_XSH;
    float* bs = (float*)(ws + 32*C1_KP);

    const int tid = threadIdx.x, lane = tid & 31, wp = tid >> 5;
    const int b = blockIdx.z;
    const int iy0 = blockIdx.y*16, ix0 = blockIdx.x*32;
    const int gr = lane >> 2, gc = lane & 3;

    if (tid < 4) xs1[4428 + tid] = __float2half_rn(0.f);
    for (int i = tid; i < C1_XSH; i += 256) {
        float v = 0.f;
        if (i < 4368) {
            int p = i >> 2, ic = i & 3;
            int yy = p / 42, xx = p - yy*42;
            if (ic < 3)
                v = x[(((size_t)b*3 + ic)*170 + iy0 + yy)*170 + ix0 + xx];
        }
        __half h = __float2half_rn(v);
        xs0[i] = h;
        if (i >= 4) xs1[i-4] = h;
    }
    for (int i = tid; i < 32*528; i += 256) {
        int oc = i / 528, kl = i - oc*528;
        int kh = kl / 48, r = kl - kh*48;
        int kw = r >> 2, ic = r & 3;
        float v = (ic < 3 && kw < 11) ? w[oc*363 + ic*121 + kh*11 + kw] : 0.f;
        ws[oc*C1_KP + kl] = __float2half_rn(v);
    }
    if (tid < 32) bs[tid] = bias[tid];
    __syncthreads();

    float acc[4][4][4];
#pragma unroll
    for (int m = 0; m < 4; m++)
#pragma unroll
        for (int n = 0; n < 4; n++)
#pragma unroll
            for (int q = 0; q < 4; q++) acc[m][n][q] = 0.f;

    const int arow = lane & 15;
    const int acol = (lane >> 4) * 8;
    const int boc  = (lane & 7) | ((lane >> 4) << 3);
    const int bk   = ((lane >> 3) & 1) * 8;
    const uint32_t xsb = s2u(xs0);
    uint32_t aaddr[4];
#pragma unroll
    for (int mt = 0; mt < 4; mt++) {
        int t = wp*4 + mt;
        int py = t >> 1, pxh = (t & 1)*16;
        int q = pxh + arow;
        int par = q & 1;
        aaddr[mt] = xsb + (((py*42 + q - par)*4 + acol)*2) + par*(C1_XSH*2);
    }
    const uint32_t baddr0 = s2u(ws) + (boc*C1_KP + bk)*2;
    const uint32_t baddr1 = baddr0 + 16*C1_KP*2;

    for (int j = 0; j < 33; j++) {
        int kh = j / 3, sub = j - kh*3;
        uint32_t aoff = (kh*42 + sub*4)*8;
        uint32_t c0,c1,c2,c3, d0,d1,d2,d3;
        ldsm4(c0,c1,c2,c3, baddr0 + j*32);
        ldsm4(d0,d1,d2,d3, baddr1 + j*32);
#pragma unroll
        for (int mt = 0; mt < 4; mt++) {
            uint32_t a0,a1,a2,a3;
            ldsm4(a0,a1,a2,a3, aaddr[mt] + aoff);
            mma16(acc[mt][0], a0,a1,a2,a3, c0,c1);
            mma16(acc[mt][1], a0,a1,a2,a3, c2,c3);
            mma16(acc[mt][2], a0,a1,a2,a3, d0,d1);
            mma16(acc[mt][3], a0,a1,a2,a3, d2,d3);
        }
    }
#pragma unroll
    for (int mt = 0; mt < 4; mt++) {
        int t = wp*4 + mt;
        int yp = iy0 + (t >> 1), xp = ix0 + (t & 1)*16 + gr;
        __half* o = out + (((size_t)b*160 + yp)*160 + xp)*32;
#pragma unroll
        for (int nt = 0; nt < 4; nt++) {
            int oc = nt*8 + gc*2;
            *(half2*)&o[oc] = __floats2half2_rn(
                acc[mt][nt][0] + bs[oc], acc[mt][nt][1] + bs[oc+1]);
            *(half2*)&o[8*32 + oc] = __floats2half2_rn(
                acc[mt][nt][2] + bs[oc], acc[mt][nt][3] + bs[oc+1]);
        }
    }
}

// =====================================================================
// region (fp16 mma + ldmatrix): in/out NHWC half
// =====================================================================
#define RG_CH 3888
#define RG_KP 392
__global__ void __launch_bounds__(256) region_h(
    const __half* __restrict__ in,
    const float* __restrict__ rl_gamma, const float* __restrict__ rl_beta,
    const float* __restrict__ rl_mean,  const float* __restrict__ rl_var,
    const float* __restrict__ rl_cw,    const float* __restrict__ rl_cb,
    const float* __restrict__ bn_g, const float* __restrict__ bn_b,
    const float* __restrict__ bn_m, const float* __restrict__ bn_v,
    __half* __restrict__ out)
{
    extern __shared__ __half smh[];
    __half* act = smh;                  // 4*3888
    __half* ws  = smh + 4*RG_CH;        // 32*392
    __shared__ float sc[32], sh[32], s2[32], t2[32], cb[32];

    const int blk = blockIdx.x;
    const int b = blk >> 6;
    const int patch = blk & 63;
    const int gi = patch >> 3, gj = patch & 7;
    const int kidx = gj*(gi+1);
    const int tid = threadIdx.x, lane = tid & 31, wp = tid >> 5;
    const int gr = lane >> 2, gc = lane & 3;

    if (tid < 32) {
        float g = rl_gamma[kidx*32+tid];
        float s = g * rsqrtf(rl_var[kidx*32+tid] + EPS);
        sc[tid] = s;
        sh[tid] = rl_beta[kidx*32+tid] - rl_mean[kidx*32+tid]*s;
        float ss = bn_g[tid] * rsqrtf(bn_v[tid] + EPS);
        s2[tid] = ss;
        t2[tid] = bn_b[tid] - bn_m[tid]*ss;
        cb[tid] = rl_cb[kidx*32+tid];
    }
    {
        uint32_t* az = (uint32_t*)act;
        for (int i = tid; i < 2*RG_CH; i += 256) az[i] = 0u;
    }
    __syncthreads();

    const __half* inb = in + (size_t)b*160*160*32;
    for (int i = tid; i < 400*32; i += 256) {
        int pix = i >> 5, ic = i & 31;
        int y = pix / 20, xx = pix - y*20;
        float v = __half2float(inb[((size_t)(gi*20+y)*160 + gj*20+xx)*32 + ic]);
        float a = fmaxf(fmaf(v, sc[ic], sh[ic]), 0.f);
        act[(ic >> 3)*RG_CH + ((y+1)*22 + (xx+1))*8 + (ic & 7)] = __float2half_rn(a);
    }
    for (int i = tid; i < 32*384; i += 256) {
        int oc = i / 384, kp = i - oc*384;
        int j = kp >> 4, loc = kp & 15;
        int kxl = loc >> 3, ic8 = loc & 7;
        int c = j / 6, r = j - c*6;
        int ky = r >> 1, kx = (r & 1)*2 + kxl;
        float v = (kx < 3) ?
            rl_cw[(size_t)kidx*9216 + oc*288 + (c*8 + ic8)*9 + ky*3 + kx] : 0.f;
        ws[oc*RG_KP + kp] = __float2half_rn(v);
    }
    __syncthreads();

    const int ntiles = (wp == 0) ? 4 : 3;
    const int arow = lane & 15;
    const int acol = (lane >> 4) * 8;
    const int boc  = (lane & 7) | ((lane >> 4) << 3);
    const int bk   = ((lane >> 3) & 1) * 8;
    uint32_t aaddr[4];
#pragma unroll
    for (int ti = 0; ti < 4; ti++) {
        int t = wp + 8*ti;
        int p = (t < 25) ? t*16 + arow : arow;
        int pixbase = (p/20)*22 + (p%20);
        aaddr[ti] = s2u(act) + (pixbase*8 + acol)*2;
    }
    const uint32_t baddr0 = s2u(ws) + (boc*RG_KP + bk)*2;
    const uint32_t baddr1 = baddr0 + 16*RG_KP*2;

    float acc[4][4][4];
#pragma unroll
    for (int m = 0; m < 4; m++)
#pragma unroll
        for (int n = 0; n < 4; n++)
#pragma unroll
            for (int q = 0; q < 4; q++) acc[m][n][q] = 0.f;

    for (int j = 0; j < 24; j++) {
        int c = j / 6, r = j - c*6;
        int ky = r >> 1, kx0 = (r & 1)*2;
        uint32_t aoff = (c*RG_CH + (ky*22 + kx0)*8)*2;
        uint32_t b0,b1,b2,b3, c0,c1,c2,c3;
        ldsm4(b0,b1,b2,b3, baddr0 + j*32);
        ldsm4(c0,c1,c2,c3, baddr1 + j*32);
#pragma unroll
        for (int ti = 0; ti < 4; ti++) {
            if (ti >= ntiles) break;
            uint32_t a0,a1,a2,a3;
            ldsm4(a0,a1,a2,a3, aaddr[ti] + aoff);
            mma16(acc[ti][0], a0,a1,a2,a3, b0,b1);
            mma16(acc[ti][1], a0,a1,a2,a3, b2,b3);
            mma16(acc[ti][2], a0,a1,a2,a3, c0,c1);
            mma16(acc[ti][3], a0,a1,a2,a3, c2,c3);
        }
    }
    __syncthreads();

    float* res = (float*)smh;          // 12800 floats aliases act+ws
#pragma unroll
    for (int ti = 0; ti < 4; ti++) {
        if (ti >= ntiles) break;
        int t = wp + 8*ti;
        int p0 = t*16 + gr, p1 = p0 + 8;
#pragma unroll
        for (int nt = 0; nt < 4; nt++) {
            int oc0 = nt*8 + 2*gc;
            res[oc0*400 + p0]     = acc[ti][nt][0];
            res[(oc0+1)*400 + p0] = acc[ti][nt][1];
            res[oc0*400 + p1]     = acc[ti][nt][2];
            res[(oc0+1)*400 + p1] = acc[ti][nt][3];
        }
    }
    __syncthreads();

    for (int item = tid; item < 3200; item += 256) {
        int oc = item / 100, pos = item - oc*100;
        int py = pos / 10, px = pos - py*10;
        float bv = cb[oc];
        const __half* xrb = inb + ((size_t)(gi*20 + 2*py)*160 + gj*20 + 2*px)*32 + oc;
        int p = (2*py)*20 + 2*px;
        float v0 = fmaxf(res[oc*400 + p]      + bv + __half2float(xrb[0]),        0.f);
        float v1 = fmaxf(res[oc*400 + p + 1]  + bv + __half2float(xrb[32]),       0.f);
        float v2 = fmaxf(res[oc*400 + p + 20] + bv + __half2float(xrb[160*32]),   0.f);
        float v3 = fmaxf(res[oc*400 + p + 21] + bv + __half2float(xrb[160*32+32]),0.f);
        float mx = fmaxf(fmaxf(v0, v1), fmaxf(v2, v3));
        out[((size_t)(b*80 + gi*10 + py)*80 + gj*10 + px)*32 + oc] =
            __float2half_rn(fmaf(mx, s2[oc], t2[oc]));
    }
}

// =====================================================================
// conv2/conv3 (fp16 mma + ldmatrix): NHWC half input, 8x8, 16 oc.
// OUT_NHWC=1 -> half NHWC out; else float NCHW out.
// =====================================================================
#define C2_KP 520
template<int CIN, int HIN, int WIN, int HOUT, int WOUT, int OUT_NHWC>
__global__ void __launch_bounds__(256) conv_nhwc(
    const __half* __restrict__ in, const float* __restrict__ w,
    const float* __restrict__ bias, void* __restrict__ outv)
{
    extern __shared__ __half smh[];
    __half* xs = smh;                   // 4240
    __half* ws = smh + 4240;            // 16*520
    float* bs = (float*)(ws + 16*C2_KP);

    const int tid = threadIdx.x, lane = tid & 31, wp = tid >> 5;
    const int b = blockIdx.z;
    const int iy0 = blockIdx.y*16, ix0 = blockIdx.x*16;
    const int gr = lane >> 2, gc = lane & 3;

    if (tid < 16) bs[tid] = bias[tid];

    float acc[2][2][4];
#pragma unroll
    for (int m = 0; m < 2; m++)
#pragma unroll
        for (int n = 0; n < 2; n++)
#pragma unroll
            for (int q = 0; q < 4; q++) acc[m][n][q] = 0.f;

    const int arow = lane & 15;
    const int acol = (lane >> 4) * 8;
    const int boc  = (lane & 7) | ((lane >> 4) << 3);
    const int bk   = ((lane >> 3) & 1) * 8;
    uint32_t aaddr[2];
#pragma unroll
    for (int mt = 0; mt < 2; mt++)
        aaddr[mt] = s2u(xs) + (((wp*2 + mt)*23 + arow)*8 + acol)*2;
    const uint32_t baddr = s2u(ws) + (boc*C2_KP + bk)*2;

    for (int cc = 0; cc < CIN; cc += 8) {
        __syncthreads();
        // stage: one uint4 (8 halves) per pixel
        for (int i = tid; i < 529; i += 256) {
            int yy = i / 23, xx = i - yy*23;
            int gy = iy0 + yy, gx = ix0 + xx;
            uint4 v = make_uint4(0u,0u,0u,0u);
            if (gy < HIN && gx < WIN)
                v = *(const uint4*)&in[((size_t)(b*HIN + gy)*WIN + gx)*CIN + cc];
            *(uint4*)&xs[i*8] = v;
        }
        for (int i = tid; i < 16*512; i += 256) {
            int oc = i >> 9, kl = i & 511;
            int kh = kl >> 6, kw = (kl >> 3) & 7, ic = kl & 7;
            ws[oc*C2_KP + kl] = __float2half_rn(
                w[((size_t)oc*CIN + cc + ic)*64 + kh*8 + kw]);
        }
        __syncthreads();

        for (int j = 0; j < 32; j++) {
            int kh = j >> 2, kw0 = (j & 3)*2;
            uint32_t aoff = (kh*23 + kw0)*16;
            uint32_t b0,b1,b2,b3;
            ldsm4(b0,b1,b2,b3, baddr + j*32);
#pragma unroll
            for (int mt = 0; mt < 2; mt++) {
                uint32_t a0,a1,a2,a3;
                ldsm4(a0,a1,a2,a3, aaddr[mt] + aoff);
                mma16(acc[mt][0], a0,a1,a2,a3, b0,b1);
                mma16(acc[mt][1], a0,a1,a2,a3, b2,b3);
            }
        }
    }

#pragma unroll
    for (int mt = 0; mt < 2; mt++) {
        int yp = iy0 + wp*2 + mt;
        int xp = ix0 + gr;
        if (yp >= HOUT) continue;
        if (OUT_NHWC) {
            __half* o = (__half*)outv + ((size_t)(b*HOUT + yp)*WOUT + xp)*16;
#pragma unroll
            for (int nt = 0; nt < 2; nt++) {
                int oc = nt*8 + gc*2;
                if (xp < WOUT)
                    *(half2*)&o[oc] = __floats2half2_rn(
                        fmaxf(acc[mt][nt][0] + bs[oc],   0.f),
                        fmaxf(acc[mt][nt][1] + bs[oc+1], 0.f));
                if (xp + 8 < WOUT)
                    *(half2*)&o[8*16 + oc] = __floats2half2_rn(
                        fmaxf(acc[mt][nt][2] + bs[oc],   0.f),
                        fmaxf(acc[mt][nt][3] + bs[oc+1], 0.f));
            }
        } else {
            float* outp = (float*)outv;
            const size_t cstride = (size_t)HOUT*WOUT;
#pragma unroll
            for (int nt = 0; nt < 2; nt++) {
                int oc = nt*8 + gc*2;
                float* o0 = outp + (((size_t)b*16 + oc)*HOUT + yp)*WOUT + xp;
                if (xp < WOUT) {
                    o0[0]       = fmaxf(acc[mt][nt][0] + bs[oc],   0.f);
                    o0[cstride] = fmaxf(acc[mt][nt][1] + bs[oc+1], 0.f);
                }
                if (xp + 8 < WOUT) {
                    o0[8]         = fmaxf(acc[mt][nt][2] + bs[oc],   0.f);
                    o0[cstride+8] = fmaxf(acc[mt][nt][3] + bs[oc+1], 0.f);
                }
            }
        }
    }
}

// =====================================================================
// conv4/conv5 (tf32): NCHW float, stride support — unchanged
// =====================================================================
template<int CIN, int KS, int STRIDE, int HIN, int WIN, int HOUT, int WOUT>
__global__ void __launch_bounds__(256) conv_tcS(
    const float* __restrict__ in, const float* __restrict__ w,
    const float* __restrict__ bias, float* __restrict__ out)
{
    constexpr int TIW = 15*STRIDE + KS;
    constexpr int KCH = 8*KS*KS;
    constexpr int KP  = KCH + 4;
    extern __shared__ uint32_t sm_u[];
    uint32_t* xs = sm_u;
    uint32_t* ws = xs + 8*TIW*TIW;
    int* lut = (int*)(ws + 16*KP);
    float* bs = (float*)(lut + KCH);

    const int tid = threadIdx.x, lane = tid & 31, wp = tid >> 5;
    const int b = blockIdx.z;
    const int iy0in = blockIdx.y*16*STRIDE, ix0in = blockIdx.x*16*STRIDE;

    for (int i = tid; i < KCH; i += 256) {
        int cl = i / (KS*KS), r = i - cl*(KS*KS);
        lut[i] = cl*(TIW*TIW) + (r/KS)*TIW + (r%KS);
    }
    if (tid < 16) bs[tid] = bias[tid];

    float acc[2][2][4];
#pragma unroll
    for (int m = 0; m < 2; m++)
#pragma unroll
        for (int n = 0; n < 2; n++)
#pragma unroll
            for (int q = 0; q < 4; q++) acc[m][n][q] = 0.f;

    const int gr = lane >> 2, gc = lane & 3;
    int mb[2];
#pragma unroll
    for (int i = 0; i < 2; i++)
        mb[i] = (STRIDE*(wp*2 + i))*TIW + STRIDE*gr;
    const int a1off = 8*STRIDE;

    for (int cc = 0; cc < CIN; cc += 8) {
        __syncthreads();
        for (int i = tid; i < 8*TIW*TIW; i += 256) {
            int cl = i / (TIW*TIW), r = i - cl*(TIW*TIW);
            int yy = r / TIW, xx = r - yy*TIW;
            int gy = iy0in + yy, gx = ix0in + xx;
            float v = 0.f;
            if (gy < HIN && gx < WIN)
                v = in[(((size_t)b*CIN + cc + cl)*HIN + gy)*WIN + gx];
            xs[i] = f2tf(v);
        }
        for (int i = tid; i < 16*KCH; i += 256) {
            int oc = i / KCH, kl = i - oc*KCH;
            int cl = kl / (KS*KS), kk = kl - cl*(KS*KS);
            ws[oc*KP + kl] = f2tf(w[((size_t)oc*CIN + cc + cl)*(KS*KS) + kk]);
        }
        __syncthreads();

        for (int k0 = 0; k0 < KCH; k0 += 8) {
            int o1 = lut[k0 + gc], o2 = lut[k0 + gc + 4];
            uint32_t bf0[2], bf1[2];
#pragma unroll
            for (int nt = 0; nt < 2; nt++) {
                const uint32_t* wp_ = &ws[(nt*8 + gr)*KP + k0];
                bf0[nt] = wp_[gc]; bf1[nt] = wp_[gc + 4];
            }
#pragma unroll
            for (int mt = 0; mt < 2; mt++) {
                uint32_t a0 = xs[mb[mt] + o1], a1 = xs[mb[mt] + a1off + o1];
                uint32_t a2 = xs[mb[mt] + o2], a3 = xs[mb[mt] + a1off + o2];
#pragma unroll
                for (int nt = 0; nt < 2; nt++)
                    mma8(acc[mt][nt], a0, a1, a2, a3, bf0[nt], bf1[nt]);
            }
        }
    }

    const size_t cstride = (size_t)HOUT*WOUT;
#pragma unroll
    for (int mt = 0; mt < 2; mt++) {
        int yp = blockIdx.y*16 + wp*2 + mt;
        int xp = blockIdx.x*16 + gr;
        if (yp < HOUT) {
#pragma unroll
            for (int nt = 0; nt < 2; nt++) {
                int oc = nt*8 + gc*2;
                float* o0 = out + (((size_t)b*16 + oc)*HOUT + yp)*WOUT + xp;
                if (xp < WOUT) {
                    o0[0]       = fmaxf(acc[mt][nt][0] + bs[oc],   0.f);
                    o0[cstride] = fmaxf(acc[mt][nt][1] + bs[oc+1], 0.f);
                }
                if (xp + 8 < WOUT) {
                    o0[8]         = fmaxf(acc[mt][nt][2] + bs[oc],   0.f);
                    o0[cstride+8] = fmaxf(acc[mt][nt][3] + bs[oc+1], 0.f);
                }
            }
        }
    }
}

// =====================================================================
// fc (tf32) — unchanged
// =====================================================================
__global__ void __launch_bounds__(256) fc_tc(
    const float* __restrict__ x, const float* __restrict__ w,
    float* __restrict__ part, int N, int K, int klen)
{
    __shared__ uint32_t as[32*68];
    __shared__ uint32_t bsm[128*68];

    const int tid = threadIdx.x, lane = tid & 31, wp = tid >> 5;
    const int n0 = blockIdx.x*128;
    const int kstart = blockIdx.y*klen;
    const int gr = lane >> 2, gc = lane & 3;
    const int nb = wp*16;

    float acc[2][2][4];
#pragma unroll
    for (int m = 0; m < 2; m++)
#pragma unroll
        for (int n = 0; n < 2; n++)
#pragma unroll
            for (int q = 0; q < 4; q++) acc[m][n][q] = 0.f;

    for (int kc = 0; kc < klen; kc += 64) {
        int cl = min(64, klen - kc);
        __syncthreads();
        for (int i = tid; i < 2048; i += 256) {
            int m = i >> 6, k = i & 63;
            float v = (k < cl) ? x[(size_t)m*K + kstart + kc + k] : 0.f;
            as[m*68 + k] = f2tf(v);
        }
        for (int i = tid; i < 8192; i += 256) {
            int n = i >> 6, k = i & 63;
            float v = (k < cl) ? w[(size_t)(n0 + n)*K + kstart + kc + k] : 0.f;
            bsm[n*68 + k] = f2tf(v);
        }
        __syncthreads();

#pragma unroll
        for (int k0 = 0; k0 < 64; k0 += 8) {
            uint32_t a0[2], a1[2], a2[2], a3[2];
#pragma unroll
            for (int mt = 0; mt < 2; mt++) {
                const uint32_t* ap = &as[(mt*16 + gr)*68 + k0];
                a0[mt] = ap[gc];        a2[mt] = ap[gc + 4];
                a1[mt] = ap[8*68 + gc]; a3[mt] = ap[8*68 + gc + 4];
            }
#pragma unroll
            for (int nt = 0; nt < 2; nt++) {
                const uint32_t* bp = &bsm[(nb + nt*8 + gr)*68 + k0];
                uint32_t b0 = bp[gc], b1 = bp[gc + 4];
#pragma unroll
                for (int mt = 0; mt < 2; mt++)
                    mma8(acc[mt][nt], a0[mt], a1[mt], a2[mt], a3[mt], b0, b1);
            }
        }
    }

    float* pr = part + (size_t)blockIdx.y*32*N;
#pragma unroll
    for (int mt = 0; mt < 2; mt++) {
#pragma unroll
        for (int nt = 0; nt < 2; nt++) {
            int n = n0 + nb + nt*8 + 2*gc;
            int m0 = mt*16 + gr;
            *(float2*)&pr[(size_t)m0*N + n]     = make_float2(acc[mt][nt][0], acc[mt][nt][1]);
            *(float2*)&pr[(size_t)(m0+8)*N + n] = make_float2(acc[mt][nt][2], acc[mt][nt][3]);
        }
    }
}

__global__ void fc_reduce(const float* __restrict__ part,
                          const float* __restrict__ bias,
                          float* __restrict__ out, int N, int KT, int do_relu)
{
    int i = blockIdx.x*256 + threadIdx.x;
    if (i >= 32*N) return;
    int n = i % N;
    float s = bias[n];
    for (int kt = 0; kt < KT; kt++) s += part[(size_t)kt*32*N + i];
    out[i] = do_relu ? fmaxf(s, 0.f) : s;
}

__global__ void __launch_bounds__(768) fc3_softmax(
    const float* __restrict__ x, const float* __restrict__ w,
    const float* __restrict__ bias, float* __restrict__ out)
{
    __shared__ float lg[24];
    const int b = blockIdx.x;
    const int tid = threadIdx.x;
    const int wo = tid >> 5, lane = tid & 31;

    const float* xr = x + (size_t)b*2048;
    const float* wr = w + (size_t)wo*2048;
    float s = 0.f;
    for (int k = lane; k < 2048; k += 32) s = fmaf(wr[k], xr[k], s);
#pragma unroll
    for (int off = 16; off; off >>= 1) s += __shfl_xor_sync(0xffffffffu, s, off);
    if (lane == 0) lg[wo] = s + bias[wo];
    __syncthreads();

    if (tid < 24) {
        int a = tid % 12;
        float z0 = lg[a], z1 = lg[12 + a];
        float m = fmaxf(z0, z1);
        float lse = m + logf(expf(z0 - m) + expf(z1 - m));
        out[b*24 + tid] = lg[tid] - lse;
    }
}

// =====================================================================
// launch
// =====================================================================
extern "C" void kernel_launch(void* const* d_in, const int* in_sizes, int n_in,
                              void* d_out, int out_size)
{
    const float* x        = (const float*)d_in[0];
    const float* conv1_w  = (const float*)d_in[1];
    const float* conv1_b  = (const float*)d_in[2];
    const float* rl_gamma = (const float*)d_in[3];
    const float* rl_beta  = (const float*)d_in[4];
    const float* rl_mean  = (const float*)d_in[5];
    const float* rl_var   = (const float*)d_in[6];
    const float* rl_cw    = (const float*)d_in[7];
    const float* rl_cb    = (const float*)d_in[8];
    const float* bn_gamma = (const float*)d_in[9];
    const float* bn_beta  = (const float*)d_in[10];
    const float* bn_mean  = (const float*)d_in[11];
    const float* bn_var   = (const float*)d_in[12];
    const float* conv2_w  = (const float*)d_in[13];
    const float* conv2_b  = (const float*)d_in[14];
    const float* conv3_w  = (const float*)d_in[15];
    const float* conv3_b  = (const float*)d_in[16];
    const float* conv4_w  = (const float*)d_in[17];
    const float* conv4_b  = (const float*)d_in[18];
    const float* conv5_w  = (const float*)d_in[19];
    const float* conv5_b  = (const float*)d_in[20];
    const float* fc1_w    = (const float*)d_in[21];
    const float* fc1_b    = (const float*)d_in[22];
    const float* fc2_w    = (const float*)d_in[23];
    const float* fc2_b    = (const float*)d_in[24];
    const float* fc3_w    = (const float*)d_in[25];
    const float* fc3_b    = (const float*)d_in[26];
    float* out = (float*)d_out;

    __half *b1h, *b2h, *b3h;
    float *b4,*b5,*b6,*pt,*f1,*f2;
    cudaGetSymbolAddress((void**)&b1h, g_buf1h);
    cudaGetSymbolAddress((void**)&b2h, g_buf2h);
    cudaGetSymbolAddress((void**)&b3h, g_buf3h);
    cudaGetSymbolAddress((void**)&b4, g_buf4);
    cudaGetSymbolAddress((void**)&b5, g_buf5);
    cudaGetSymbolAddress((void**)&b6, g_buf6);
    cudaGetSymbolAddress((void**)&pt, g_part);
    cudaGetSymbolAddress((void**)&f1, g_fc1);
    cudaGetSymbolAddress((void**)&f2, g_fc2);

    const int c1_smem = (2*C1_XSH + 32*C1_KP)*2 + 32*4;
    cudaFuncSetAttribute(conv1_h,
                         cudaFuncAttributeMaxDynamicSharedMemorySize, c1_smem);
    const int reg_smem = (4*RG_CH + 32*RG_KP)*2;
    cudaFuncSetAttribute(region_h,
                         cudaFuncAttributeMaxDynamicSharedMemorySize, reg_smem);
    const int c2_smem = (4240 + 16*C2_KP)*2 + 16*4;
    cudaFuncSetAttribute(conv_nhwc<32,80,80,73,73,1>,
                         cudaFuncAttributeMaxDynamicSharedMemorySize, c2_smem);
    cudaFuncSetAttribute(conv_nhwc<16,73,73,66,66,0>,
                         cudaFuncAttributeMaxDynamicSharedMemorySize, c2_smem);
    const int c4_smem = (8*36*36 + 16*292 + 288 + 16) * 4;
    cudaFuncSetAttribute(conv_tcS<16,6,2,66,66,31,31>,
                         cudaFuncAttributeMaxDynamicSharedMemorySize, c4_smem);
    const int c5_smem = (8*20*20 + 16*204 + 200 + 16) * 4;
    cudaFuncSetAttribute(conv_tcS<16,5,1,31,31,27,27>,
                         cudaFuncAttributeMaxDynamicSharedMemorySize, c5_smem);

    // 1. conv1 -> NHWC half
    conv1_h<<<dim3(5,10,BATCH), 256, c1_smem>>>(x, conv1_w, conv1_b, b1h);

    // 2. region (NHWC half in/out)
    region_h<<<BATCH*64, 256, reg_smem>>>(
        b1h, rl_gamma, rl_beta, rl_mean, rl_var, rl_cw, rl_cb,
        bn_gamma, bn_beta, bn_mean, bn_var, b2h);

    // 3. conv2: NHWC half -> NHWC half
    conv_nhwc<32,80,80,73,73,1><<<dim3(5,5,BATCH), 256, c2_smem>>>(
        b2h, conv2_w, conv2_b, b3h);

    // 4. conv3: NHWC half -> NCHW float
    conv_nhwc<16,73,73,66,66,0><<<dim3(5,5,BATCH), 256, c2_smem>>>(
        b3h, conv3_w, conv3_b, b4);

    // 5. conv4 (tf32 NCHW)
    conv_tcS<16,6,2,66,66,31,31><<<dim3(2,2,BATCH), 256, c4_smem>>>(
        b4, conv4_w, conv4_b, b5);

    // 6. conv5
    conv_tcS<16,5,1,31,31,27,27><<<dim3(2,2,BATCH), 256, c5_smem>>>(
        b5, conv5_w, conv5_b, b6);

    // 7. fc1
    fc_tc<<<dim3(32,24), 256>>>(b6, fc1_w, pt, 4096, 11664, 486);
    fc_reduce<<<512, 256>>>(pt, fc1_b, f1, 4096, 24, 1);

    // 8. fc2
    fc_tc<<<dim3(16,16), 256>>>(f1, fc2_w, pt, 2048, 4096, 256);
    fc_reduce<<<256, 256>>>(pt, fc2_b, f2, 2048, 16, 1);

    // 9. fc3 + log_softmax
    fc3_softmax<<<BATCH, 768>>>(f2, fc3_w, fc3_b, out);
}

// round 12
// speedup vs baseline: 1.1559x; 1.1559x over previous
#include <cuda_runtime.h>
#include <cuda_fp16.h>
#include <cuda_bf16.h>
#include <math.h>
#include <stdint.h>

#define BATCH 32
#define EPS 1e-5f

__device__ __forceinline__ uint32_t f2tf(float f) {
    uint32_t r; asm("cvt.rna.tf32.f32 %0,%1;" : "=r"(r) : "f"(f)); return r;
}
__device__ __forceinline__ void mma8(float* c, uint32_t a0, uint32_t a1,
                                     uint32_t a2, uint32_t a3,
                                     uint32_t b0, uint32_t b1) {
    asm("mma.sync.aligned.m16n8k8.row.col.f32.tf32.tf32.f32 "
        "{%0,%1,%2,%3},{%4,%5,%6,%7},{%8,%9},{%0,%1,%2,%3};"
        : "+f"(c[0]), "+f"(c[1]), "+f"(c[2]), "+f"(c[3])
        : "r"(a0), "r"(a1), "r"(a2), "r"(a3), "r"(b0), "r"(b1));
}
__device__ __forceinline__ void mma16(float* c, uint32_t a0, uint32_t a1,
                                      uint32_t a2, uint32_t a3,
                                      uint32_t b0, uint32_t b1) {
    asm("mma.sync.aligned.m16n8k16.row.col.f32.f16.f16.f32 "
        "{%0,%1,%2,%3},{%4,%5,%6,%7},{%8,%9},{%0,%1,%2,%3};"
        : "+f"(c[0]), "+f"(c[1]), "+f"(c[2]), "+f"(c[3])
        : "r"(a0), "r"(a1), "r"(a2), "r"(a3), "r"(b0), "r"(b1));
}
__device__ __forceinline__ uint32_t s2u(const void* p) {
    return (uint32_t)__cvta_generic_to_shared(p);
}
__device__ __forceinline__ void ldsm4(uint32_t& r0, uint32_t& r1,
                                      uint32_t& r2, uint32_t& r3, uint32_t a) {
    asm volatile("ldmatrix.sync.aligned.m8n8.x4.shared.b16 {%0,%1,%2,%3},[%4];"
        : "=r"(r0), "=r"(r1), "=r"(r2), "=r"(r3) : "r"(a));
}

// ---------------- scratch ----------------
__device__ __align__(256) __half g_buf1h[BATCH*160*160*32];  // NHWC
__device__ __align__(256) __half g_buf2h[BATCH*80*80*32];    // NHWC
__device__ __align__(256) __half g_buf3h[BATCH*73*73*16];    // NHWC
__device__ float g_buf4[BATCH*16*66*66];                     // NCHW
__device__ float g_buf5[BATCH*16*31*31];
__device__ float g_buf6[BATCH*16*27*27];
__device__ float g_part[24*32*4096];
__device__ float g_fc1[BATCH*4096];
__device__ float g_fc2[BATCH*2048];

// =====================================================================
// conv1 (fp16 mma + ldmatrix): x NCHW fp32 -> NHWC half (coalesced epi)
// =====================================================================
#define C1_KP 536
#define C1_XSH 4432
__global__ void __launch_bounds__(256) conv1_h(
    const float* __restrict__ x, const float* __restrict__ w,
    const float* __restrict__ bias, __half* __restrict__ out)
{
    extern __shared__ __half smh[];
    __half* xs0 = smh;
    __half* xs1 = smh + C1_XSH;
    __half* ws  = smh + 2*C1_XSH;
    float* bs = (float*)(ws + 32*C1_KP);

    const int tid = threadIdx.x, lane = tid & 31, wp = tid >> 5;
    const int b = blockIdx.z;
    const int iy0 = blockIdx.y*16, ix0 = blockIdx.x*32;
    const int gr = lane >> 2, gc = lane & 3;

    if (tid < 4) xs1[4428 + tid] = __float2half_rn(0.f);
    for (int i = tid; i < C1_XSH; i += 256) {
        float v = 0.f;
        if (i < 4368) {
            int p = i >> 2, ic = i & 3;
            int yy = p / 42, xx = p - yy*42;
            if (ic < 3)
                v = x[(((size_t)b*3 + ic)*170 + iy0 + yy)*170 + ix0 + xx];
        }
        __half h = __float2half_rn(v);
        xs0[i] = h;
        if (i >= 4) xs1[i-4] = h;
    }
    for (int i = tid; i < 32*528; i += 256) {
        int oc = i / 528, kl = i - oc*528;
        int kh = kl / 48, r = kl - kh*48;
        int kw = r >> 2, ic = r & 3;
        float v = (ic < 3 && kw < 11) ? w[oc*363 + ic*121 + kh*11 + kw] : 0.f;
        ws[oc*C1_KP + kl] = __float2half_rn(v);
    }
    if (tid < 32) bs[tid] = bias[tid];
    __syncthreads();

    float acc[4][4][4];
#pragma unroll
    for (int m = 0; m < 4; m++)
#pragma unroll
        for (int n = 0; n < 4; n++)
#pragma unroll
            for (int q = 0; q < 4; q++) acc[m][n][q] = 0.f;

    const int arow = lane & 15;
    const int acol = (lane >> 4) * 8;
    const int boc  = (lane & 7) | ((lane >> 4) << 3);
    const int bk   = ((lane >> 3) & 1) * 8;
    const uint32_t xsb = s2u(xs0);
    uint32_t aaddr[4];
#pragma unroll
    for (int mt = 0; mt < 4; mt++) {
        int t = wp*4 + mt;
        int py = t >> 1, pxh = (t & 1)*16;
        int q = pxh + arow;
        int par = q & 1;
        aaddr[mt] = xsb + (((py*42 + q - par)*4 + acol)*2) + par*(C1_XSH*2);
    }
    const uint32_t baddr0 = s2u(ws) + (boc*C1_KP + bk)*2;
    const uint32_t baddr1 = baddr0 + 16*C1_KP*2;

    for (int j = 0; j < 33; j++) {
        int kh = j / 3, sub = j - kh*3;
        uint32_t aoff = (kh*42 + sub*4)*8;
        uint32_t c0,c1,c2,c3, d0,d1,d2,d3;
        ldsm4(c0,c1,c2,c3, baddr0 + j*32);
        ldsm4(d0,d1,d2,d3, baddr1 + j*32);
#pragma unroll
        for (int mt = 0; mt < 4; mt++) {
            uint32_t a0,a1,a2,a3;
            ldsm4(a0,a1,a2,a3, aaddr[mt] + aoff);
            mma16(acc[mt][0], a0,a1,a2,a3, c0,c1);
            mma16(acc[mt][1], a0,a1,a2,a3, c2,c3);
            mma16(acc[mt][2], a0,a1,a2,a3, d0,d1);
            mma16(acc[mt][3], a0,a1,a2,a3, d2,d3);
        }
    }
    // ---- epilogue: smem transpose -> coalesced NHWC stores ----
    float bloc[8];
#pragma unroll
    for (int nt = 0; nt < 4; nt++) {
        bloc[2*nt]   = bs[nt*8 + gc*2];
        bloc[2*nt+1] = bs[nt*8 + gc*2 + 1];
    }
    __syncthreads();
    __half* osm = smh;                 // 512 px * 36 halves = 18432 <= 26016
#pragma unroll
    for (int mt = 0; mt < 4; mt++) {
        int t = wp*4 + mt;
        int p0 = (t >> 1)*32 + (t & 1)*16 + gr;   // pixel index in 16x32 tile
#pragma unroll
        for (int nt = 0; nt < 4; nt++) {
            int oc = nt*8 + gc*2;
            *(half2*)&osm[p0*36 + oc] = __floats2half2_rn(
                acc[mt][nt][0] + bloc[2*nt], acc[mt][nt][1] + bloc[2*nt+1]);
            *(half2*)&osm[(p0+8)*36 + oc] = __floats2half2_rn(
                acc[mt][nt][2] + bloc[2*nt], acc[mt][nt][3] + bloc[2*nt+1]);
        }
    }
    __syncthreads();
    for (int i = tid; i < 4096; i += 256) {
        int p = i >> 3, seg = i & 7;
        int py = p >> 5, px = p & 31;
        uint2 v = *(uint2*)&osm[p*36 + seg*4];
        *(uint2*)&out[(((size_t)b*160 + iy0 + py)*160 + ix0 + px)*32 + seg*4] = v;
    }
}

// =====================================================================
// region (fp16 mma + ldmatrix): NHWC half in/out; coalesced epilogue
// =====================================================================
#define RG_CH 3888
#define RG_KP 392
__global__ void __launch_bounds__(256) region_h(
    const __half* __restrict__ in,
    const float* __restrict__ rl_gamma, const float* __restrict__ rl_beta,
    const float* __restrict__ rl_mean,  const float* __restrict__ rl_var,
    const float* __restrict__ rl_cw,    const float* __restrict__ rl_cb,
    const float* __restrict__ bn_g, const float* __restrict__ bn_b,
    const float* __restrict__ bn_m, const float* __restrict__ bn_v,
    __half* __restrict__ out)
{
    extern __shared__ __half smh[];
    __half* act = smh;                  // 4*3888
    __half* ws  = smh + 4*RG_CH;        // 32*392
    __shared__ float sc[32], sh[32], s2[32], t2[32], cb[32];

    const int blk = blockIdx.x;
    const int b = blk >> 6;
    const int patch = blk & 63;
    const int gi = patch >> 3, gj = patch & 7;
    const int kidx = gj*(gi+1);
    const int tid = threadIdx.x, lane = tid & 31, wp = tid >> 5;
    const int gr = lane >> 2, gc = lane & 3;

    if (tid < 32) {
        float g = rl_gamma[kidx*32+tid];
        float s = g * rsqrtf(rl_var[kidx*32+tid] + EPS);
        sc[tid] = s;
        sh[tid] = rl_beta[kidx*32+tid] - rl_mean[kidx*32+tid]*s;
        float ss = bn_g[tid] * rsqrtf(bn_v[tid] + EPS);
        s2[tid] = ss;
        t2[tid] = bn_b[tid] - bn_m[tid]*ss;
        cb[tid] = rl_cb[kidx*32+tid];
    }
    {
        uint32_t* az = (uint32_t*)act;
        for (int i = tid; i < 2*RG_CH; i += 256) az[i] = 0u;
    }
    __syncthreads();

    const __half* inb = in + (size_t)b*160*160*32;
    for (int i = tid; i < 400*32; i += 256) {
        int pix = i >> 5, ic = i & 31;
        int y = pix / 20, xx = pix - y*20;
        float v = __half2float(inb[((size_t)(gi*20+y)*160 + gj*20+xx)*32 + ic]);
        float a = fmaxf(fmaf(v, sc[ic], sh[ic]), 0.f);
        act[(ic >> 3)*RG_CH + ((y+1)*22 + (xx+1))*8 + (ic & 7)] = __float2half_rn(a);
    }
    for (int i = tid; i < 32*384; i += 256) {
        int oc = i / 384, kp = i - oc*384;
        int j = kp >> 4, loc = kp & 15;
        int kxl = loc >> 3, ic8 = loc & 7;
        int c = j / 6, r = j - c*6;
        int ky = r >> 1, kx = (r & 1)*2 + kxl;
        float v = (kx < 3) ?
            rl_cw[(size_t)kidx*9216 + oc*288 + (c*8 + ic8)*9 + ky*3 + kx] : 0.f;
        ws[oc*RG_KP + kp] = __float2half_rn(v);
    }
    __syncthreads();

    const int ntiles = (wp == 0) ? 4 : 3;
    const int arow = lane & 15;
    const int acol = (lane >> 4) * 8;
    const int boc  = (lane & 7) | ((lane >> 4) << 3);
    const int bk   = ((lane >> 3) & 1) * 8;
    uint32_t aaddr[4];
#pragma unroll
    for (int ti = 0; ti < 4; ti++) {
        int t = wp + 8*ti;
        int p = (t < 25) ? t*16 + arow : arow;
        int pixbase = (p/20)*22 + (p%20);
        aaddr[ti] = s2u(act) + (pixbase*8 + acol)*2;
    }
    const uint32_t baddr0 = s2u(ws) + (boc*RG_KP + bk)*2;
    const uint32_t baddr1 = baddr0 + 16*RG_KP*2;

    float acc[4][4][4];
#pragma unroll
    for (int m = 0; m < 4; m++)
#pragma unroll
        for (int n = 0; n < 4; n++)
#pragma unroll
            for (int q = 0; q < 4; q++) acc[m][n][q] = 0.f;

    for (int j = 0; j < 24; j++) {
        int c = j / 6, r = j - c*6;
        int ky = r >> 1, kx0 = (r & 1)*2;
        uint32_t aoff = (c*RG_CH + (ky*22 + kx0)*8)*2;
        uint32_t b0,b1,b2,b3, c0,c1,c2,c3;
        ldsm4(b0,b1,b2,b3, baddr0 + j*32);
        ldsm4(c0,c1,c2,c3, baddr1 + j*32);
#pragma unroll
        for (int ti = 0; ti < 4; ti++) {
            if (ti >= ntiles) break;
            uint32_t a0,a1,a2,a3;
            ldsm4(a0,a1,a2,a3, aaddr[ti] + aoff);
            mma16(acc[ti][0], a0,a1,a2,a3, b0,b1);
            mma16(acc[ti][1], a0,a1,a2,a3, b2,b3);
            mma16(acc[ti][2], a0,a1,a2,a3, c0,c1);
            mma16(acc[ti][3], a0,a1,a2,a3, c2,c3);
        }
    }
    __syncthreads();

    float* res = (float*)smh;          // 32 * 401 floats = 51328 B
#pragma unroll
    for (int ti = 0; ti < 4; ti++) {
        if (ti >= ntiles) break;
        int t = wp + 8*ti;
        int p0 = t*16 + gr, p1 = p0 + 8;
#pragma unroll
        for (int nt = 0; nt < 4; nt++) {
            int oc0 = nt*8 + 2*gc;
            res[oc0*401 + p0]     = acc[ti][nt][0];
            res[(oc0+1)*401 + p0] = acc[ti][nt][1];
            res[oc0*401 + p1]     = acc[ti][nt][2];
            res[(oc0+1)*401 + p1] = acc[ti][nt][3];
        }
    }
    __syncthreads();

    // pass2: oc innermost -> coalesced NHWC store
    for (int item = tid; item < 3200; item += 256) {
        int pos = item >> 5, oc = item & 31;
        int py = pos / 10, px = pos - py*10;
        float bv = cb[oc];
        const __half* xrb = inb + ((size_t)(gi*20 + 2*py)*160 + gj*20 + 2*px)*32 + oc;
        int p = (2*py)*20 + 2*px;
        const float* rr = &res[oc*401];
        float v0 = fmaxf(rr[p]      + bv + __half2float(xrb[0]),        0.f);
        float v1 = fmaxf(rr[p + 1]  + bv + __half2float(xrb[32]),       0.f);
        float v2 = fmaxf(rr[p + 20] + bv + __half2float(xrb[160*32]),   0.f);
        float v3 = fmaxf(rr[p + 21] + bv + __half2float(xrb[160*32+32]),0.f);
        float mx = fmaxf(fmaxf(v0, v1), fmaxf(v2, v3));
        out[((size_t)(b*80 + gi*10 + py)*80 + gj*10 + px)*32 + oc] =
            __float2half_rn(fmaf(mx, s2[oc], t2[oc]));
    }
}

// =====================================================================
// conv2/conv3 (fp16 mma + ldmatrix): NHWC half in; OUT_NHWC selects out
// =====================================================================
#define C2_KP 520
template<int CIN, int HIN, int WIN, int HOUT, int WOUT, int OUT_NHWC>
__global__ void __launch_bounds__(256) conv_nhwc(
    const __half* __restrict__ in, const float* __restrict__ w,
    const float* __restrict__ bias, void* __restrict__ outv)
{
    extern __shared__ __half smh[];
    __half* xs = smh;                   // 4240
    __half* ws = smh + 4240;            // 16*520
    float* bs = (float*)(ws + 16*C2_KP);

    const int tid = threadIdx.x, lane = tid & 31, wp = tid >> 5;
    const int b = blockIdx.z;
    const int iy0 = blockIdx.y*16, ix0 = blockIdx.x*16;
    const int gr = lane >> 2, gc = lane & 3;

    if (tid < 16) bs[tid] = bias[tid];

    float acc[2][2][4];
#pragma unroll
    for (int m = 0; m < 2; m++)
#pragma unroll
        for (int n = 0; n < 2; n++)
#pragma unroll
            for (int q = 0; q < 4; q++) acc[m][n][q] = 0.f;

    const int arow = lane & 15;
    const int acol = (lane >> 4) * 8;
    const int boc  = (lane & 7) | ((lane >> 4) << 3);
    const int bk   = ((lane >> 3) & 1) * 8;
    uint32_t aaddr[2];
#pragma unroll
    for (int mt = 0; mt < 2; mt++)
        aaddr[mt] = s2u(xs) + (((wp*2 + mt)*23 + arow)*8 + acol)*2;
    const uint32_t baddr = s2u(ws) + (boc*C2_KP + bk)*2;

    for (int cc = 0; cc < CIN; cc += 8) {
        __syncthreads();
        for (int i = tid; i < 529; i += 256) {
            int yy = i / 23, xx = i - yy*23;
            int gy = iy0 + yy, gx = ix0 + xx;
            uint4 v = make_uint4(0u,0u,0u,0u);
            if (gy < HIN && gx < WIN)
                v = *(const uint4*)&in[((size_t)(b*HIN + gy)*WIN + gx)*CIN + cc];
            *(uint4*)&xs[i*8] = v;
        }
        for (int i = tid; i < 16*512; i += 256) {
            int oc = i >> 9, kl = i & 511;
            int kh = kl >> 6, kw = (kl >> 3) & 7, ic = kl & 7;
            ws[oc*C2_KP + kl] = __float2half_rn(
                w[((size_t)oc*CIN + cc + ic)*64 + kh*8 + kw]);
        }
        __syncthreads();

        for (int j = 0; j < 32; j++) {
            int kh = j >> 2, kw0 = (j & 3)*2;
            uint32_t aoff = (kh*23 + kw0)*16;
            uint32_t b0,b1,b2,b3;
            ldsm4(b0,b1,b2,b3, baddr + j*32);
#pragma unroll
            for (int mt = 0; mt < 2; mt++) {
                uint32_t a0,a1,a2,a3;
                ldsm4(a0,a1,a2,a3, aaddr[mt] + aoff);
                mma16(acc[mt][0], a0,a1,a2,a3, b0,b1);
                mma16(acc[mt][1], a0,a1,a2,a3, b2,b3);
            }
        }
    }

    if (OUT_NHWC) {
        // smem transpose -> coalesced NHWC half stores
        float b0l = bs[gc*2],     b1l = bs[gc*2+1];
        float b2l = bs[8+gc*2],   b3l = bs[8+gc*2+1];
        __syncthreads();
        __half* osm = smh;             // 256 px * 24 halves = 6144
#pragma unroll
        for (int mt = 0; mt < 2; mt++) {
            int p0 = (wp*2 + mt)*16 + gr;
            *(half2*)&osm[p0*24 + gc*2] = __floats2half2_rn(
                fmaxf(acc[mt][0][0] + b0l, 0.f), fmaxf(acc[mt][0][1] + b1l, 0.f));
            *(half2*)&osm[p0*24 + 8 + gc*2] = __floats2half2_rn(
                fmaxf(acc[mt][1][0] + b2l, 0.f), fmaxf(acc[mt][1][1] + b3l, 0.f));
            *(half2*)&osm[(p0+8)*24 + gc*2] = __floats2half2_rn(
                fmaxf(acc[mt][0][2] + b0l, 0.f), fmaxf(acc[mt][0][3] + b1l, 0.f));
            *(half2*)&osm[(p0+8)*24 + 8 + gc*2] = __floats2half2_rn(
                fmaxf(acc[mt][1][2] + b2l, 0.f), fmaxf(acc[mt][1][3] + b3l, 0.f));
        }
        __syncthreads();
        __half* o = (__half*)outv;
        for (int i = tid; i < 512; i += 256) {
            int p = i >> 1, seg = i & 1;
            int py = p >> 4, px = p & 15;
            int yp = iy0 + py, xp = ix0 + px;
            if (yp < HOUT && xp < WOUT) {
                uint4 v = *(uint4*)&osm[p*24 + seg*8];
                *(uint4*)&o[((size_t)(b*HOUT + yp)*WOUT + xp)*16 + seg*8] = v;
            }
        }
    } else {
        float* outp = (float*)outv;
        const size_t cstride = (size_t)HOUT*WOUT;
#pragma unroll
        for (int mt = 0; mt < 2; mt++) {
            int yp = iy0 + wp*2 + mt;
            int xp = ix0 + gr;
            if (yp >= HOUT) continue;
#pragma unroll
            for (int nt = 0; nt < 2; nt++) {
                int oc = nt*8 + gc*2;
                float* o0 = outp + (((size_t)b*16 + oc)*HOUT + yp)*WOUT + xp;
                if (xp < WOUT) {
                    o0[0]       = fmaxf(acc[mt][nt][0] + bs[oc],   0.f);
                    o0[cstride] = fmaxf(acc[mt][nt][1] + bs[oc+1], 0.f);
                }
                if (xp + 8 < WOUT) {
                    o0[8]         = fmaxf(acc[mt][nt][2] + bs[oc],   0.f);
                    o0[cstride+8] = fmaxf(acc[mt][nt][3] + bs[oc+1], 0.f);
                }
            }
        }
    }
}

// =====================================================================
// conv4/conv5 (tf32): NCHW float — unchanged
// =====================================================================
template<int CIN, int KS, int STRIDE, int HIN, int WIN, int HOUT, int WOUT>
__global__ void __launch_bounds__(256) conv_tcS(
    const float* __restrict__ in, const float* __restrict__ w,
    const float* __restrict__ bias, float* __restrict__ out)
{
    constexpr int TIW = 15*STRIDE + KS;
    constexpr int KCH = 8*KS*KS;
    constexpr int KP  = KCH + 4;
    extern __shared__ uint32_t sm_u[];
    uint32_t* xs = sm_u;
    uint32_t* ws = xs + 8*TIW*TIW;
    int* lut = (int*)(ws + 16*KP);
    float* bs = (float*)(lut + KCH);

    const int tid = threadIdx.x, lane = tid & 31, wp = tid >> 5;
    const int b = blockIdx.z;
    const int iy0in = blockIdx.y*16*STRIDE, ix0in = blockIdx.x*16*STRIDE;

    for (int i = tid; i < KCH; i += 256) {
        int cl = i / (KS*KS), r = i - cl*(KS*KS);
        lut[i] = cl*(TIW*TIW) + (r/KS)*TIW + (r%KS);
    }
    if (tid < 16) bs[tid] = bias[tid];

    float acc[2][2][4];
#pragma unroll
    for (int m = 0; m < 2; m++)
#pragma unroll
        for (int n = 0; n < 2; n++)
#pragma unroll
            for (int q = 0; q < 4; q++) acc[m][n][q] = 0.f;

    const int gr = lane >> 2, gc = lane & 3;
    int mb[2];
#pragma unroll
    for (int i = 0; i < 2; i++)
        mb[i] = (STRIDE*(wp*2 + i))*TIW + STRIDE*gr;
    const int a1off = 8*STRIDE;

    for (int cc = 0; cc < CIN; cc += 8) {
        __syncthreads();
        for (int i = tid; i < 8*TIW*TIW; i += 256) {
            int cl = i / (TIW*TIW), r = i - cl*(TIW*TIW);
            int yy = r / TIW, xx = r - yy*TIW;
            int gy = iy0in + yy, gx = ix0in + xx;
            float v = 0.f;
            if (gy < HIN && gx < WIN)
                v = in[(((size_t)b*CIN + cc + cl)*HIN + gy)*WIN + gx];
            xs[i] = f2tf(v);
        }
        for (int i = tid; i < 16*KCH; i += 256) {
            int oc = i / KCH, kl = i - oc*KCH;
            int cl = kl / (KS*KS), kk = kl - cl*(KS*KS);
            ws[oc*KP + kl] = f2tf(w[((size_t)oc*CIN + cc + cl)*(KS*KS) + kk]);
        }
        __syncthreads();

        for (int k0 = 0; k0 < KCH; k0 += 8) {
            int o1 = lut[k0 + gc], o2 = lut[k0 + gc + 4];
            uint32_t bf0[2], bf1[2];
#pragma unroll
            for (int nt = 0; nt < 2; nt++) {
                const uint32_t* wp_ = &ws[(nt*8 + gr)*KP + k0];
                bf0[nt] = wp_[gc]; bf1[nt] = wp_[gc + 4];
            }
#pragma unroll
            for (int mt = 0; mt < 2; mt++) {
                uint32_t a0 = xs[mb[mt] + o1], a1 = xs[mb[mt] + a1off + o1];
                uint32_t a2 = xs[mb[mt] + o2], a3 = xs[mb[mt] + a1off + o2];
#pragma unroll
                for (int nt = 0; nt < 2; nt++)
                    mma8(acc[mt][nt], a0, a1, a2, a3, bf0[nt], bf1[nt]);
            }
        }
    }

    const size_t cstride = (size_t)HOUT*WOUT;
#pragma unroll
    for (int mt = 0; mt < 2; mt++) {
        int yp = blockIdx.y*16 + wp*2 + mt;
        int xp = blockIdx.x*16 + gr;
        if (yp < HOUT) {
#pragma unroll
            for (int nt = 0; nt < 2; nt++) {
                int oc = nt*8 + gc*2;
                float* o0 = out + (((size_t)b*16 + oc)*HOUT + yp)*WOUT + xp;
                if (xp < WOUT) {
                    o0[0]       = fmaxf(acc[mt][nt][0] + bs[oc],   0.f);
                    o0[cstride] = fmaxf(acc[mt][nt][1] + bs[oc+1], 0.f);
                }
                if (xp + 8 < WOUT) {
                    o0[8]         = fmaxf(acc[mt][nt][2] + bs[oc],   0.f);
                    o0[cstride+8] = fmaxf(acc[mt][nt][3] + bs[oc+1], 0.f);
                }
            }
        }
    }
}

// =====================================================================
// fc (tf32) — unchanged
// =====================================================================
__global__ void __launch_bounds__(256) fc_tc(
    const float* __restrict__ x, const float* __restrict__ w,
    float* __restrict__ part, int N, int K, int klen)
{
    __shared__ uint32_t as[32*68];
    __shared__ uint32_t bsm[128*68];

    const int tid = threadIdx.x, lane = tid & 31, wp = tid >> 5;
    const int n0 = blockIdx.x*128;
    const int kstart = blockIdx.y*klen;
    const int gr = lane >> 2, gc = lane & 3;
    const int nb = wp*16;

    float acc[2][2][4];
#pragma unroll
    for (int m = 0; m < 2; m++)
#pragma unroll
        for (int n = 0; n < 2; n++)
#pragma unroll
            for (int q = 0; q < 4; q++) acc[m][n][q] = 0.f;

    for (int kc = 0; kc < klen; kc += 64) {
        int cl = min(64, klen - kc);
        __syncthreads();
        for (int i = tid; i < 2048; i += 256) {
            int m = i >> 6, k = i & 63;
            float v = (k < cl) ? x[(size_t)m*K + kstart + kc + k] : 0.f;
            as[m*68 + k] = f2tf(v);
        }
        for (int i = tid; i < 8192; i += 256) {
            int n = i >> 6, k = i & 63;
            float v = (k < cl) ? w[(size_t)(n0 + n)*K + kstart + kc + k] : 0.f;
            bsm[n*68 + k] = f2tf(v);
        }
        __syncthreads();

#pragma unroll
        for (int k0 = 0; k0 < 64; k0 += 8) {
            uint32_t a0[2], a1[2], a2[2], a3[2];
#pragma unroll
            for (int mt = 0; mt < 2; mt++) {
                const uint32_t* ap = &as[(mt*16 + gr)*68 + k0];
                a0[mt] = ap[gc];        a2[mt] = ap[gc + 4];
                a1[mt] = ap[8*68 + gc]; a3[mt] = ap[8*68 + gc + 4];
            }
#pragma unroll
            for (int nt = 0; nt < 2; nt++) {
                const uint32_t* bp = &bsm[(nb + nt*8 + gr)*68 + k0];
                uint32_t b0 = bp[gc], b1 = bp[gc + 4];
#pragma unroll
                for (int mt = 0; mt < 2; mt++)
                    mma8(acc[mt][nt], a0[mt], a1[mt], a2[mt], a3[mt], b0, b1);
            }
        }
    }

    float* pr = part + (size_t)blockIdx.y*32*N;
#pragma unroll
    for (int mt = 0; mt < 2; mt++) {
#pragma unroll
        for (int nt = 0; nt < 2; nt++) {
            int n = n0 + nb + nt*8 + 2*gc;
            int m0 = mt*16 + gr;
            *(float2*)&pr[(size_t)m0*N + n]     = make_float2(acc[mt][nt][0], acc[mt][nt][1]);
            *(float2*)&pr[(size_t)(m0+8)*N + n] = make_float2(acc[mt][nt][2], acc[mt][nt][3]);
        }
    }
}

__global__ void fc_reduce(const float* __restrict__ part,
                          const float* __restrict__ bias,
                          float* __restrict__ out, int N, int KT, int do_relu)
{
    int i = blockIdx.x*256 + threadIdx.x;
    if (i >= 32*N) return;
    int n = i % N;
    float s = bias[n];
    for (int kt = 0; kt < KT; kt++) s += part[(size_t)kt*32*N + i];
    out[i] = do_relu ? fmaxf(s, 0.f) : s;
}

__global__ void __launch_bounds__(768) fc3_softmax(
    const float* __restrict__ x, const float* __restrict__ w,
    const float* __restrict__ bias, float* __restrict__ out)
{
    __shared__ float lg[24];
    const int b = blockIdx.x;
    const int tid = threadIdx.x;
    const int wo = tid >> 5, lane = tid & 31;

    const float* xr = x + (size_t)b*2048;
    const float* wr = w + (size_t)wo*2048;
    float s = 0.f;
    for (int k = lane; k < 2048; k += 32) s = fmaf(wr[k], xr[k], s);
#pragma unroll
    for (int off = 16; off; off >>= 1) s += __shfl_xor_sync(0xffffffffu, s, off);
    if (lane == 0) lg[wo] = s + bias[wo];
    __syncthreads();

    if (tid < 24) {
        int a = tid % 12;
        float z0 = lg[a], z1 = lg[12 + a];
        float m = fmaxf(z0, z1);
        float lse = m + logf(expf(z0 - m) + expf(z1 - m));
        out[b*24 + tid] = lg[tid] - lse;
    }
}

// =====================================================================
// launch
// =====================================================================
extern "C" void kernel_launch(void* const* d_in, const int* in_sizes, int n_in,
                              void* d_out, int out_size)
{
    const float* x        = (const float*)d_in[0];
    const float* conv1_w  = (const float*)d_in[1];
    const float* conv1_b  = (const float*)d_in[2];
    const float* rl_gamma = (const float*)d_in[3];
    const float* rl_beta  = (const float*)d_in[4];
    const float* rl_mean  = (const float*)d_in[5];
    const float* rl_var   = (const float*)d_in[6];
    const float* rl_cw    = (const float*)d_in[7];
    const float* rl_cb    = (const float*)d_in[8];
    const float* bn_gamma = (const float*)d_in[9];
    const float* bn_beta  = (const float*)d_in[10];
    const float* bn_mean  = (const float*)d_in[11];
    const float* bn_var   = (const float*)d_in[12];
    const float* conv2_w  = (const float*)d_in[13];
    const float* conv2_b  = (const float*)d_in[14];
    const float* conv3_w  = (const float*)d_in[15];
    const float* conv3_b  = (const float*)d_in[16];
    const float* conv4_w  = (const float*)d_in[17];
    const float* conv4_b  = (const float*)d_in[18];
    const float* conv5_w  = (const float*)d_in[19];
    const float* conv5_b  = (const float*)d_in[20];
    const float* fc1_w    = (const float*)d_in[21];
    const float* fc1_b    = (const float*)d_in[22];
    const float* fc2_w    = (const float*)d_in[23];
    const float* fc2_b    = (const float*)d_in[24];
    const float* fc3_w    = (const float*)d_in[25];
    const float* fc3_b    = (const float*)d_in[26];
    float* out = (float*)d_out;

    __half *b1h, *b2h, *b3h;
    float *b4,*b5,*b6,*pt,*f1,*f2;
    cudaGetSymbolAddress((void**)&b1h, g_buf1h);
    cudaGetSymbolAddress((void**)&b2h, g_buf2h);
    cudaGetSymbolAddress((void**)&b3h, g_buf3h);
    cudaGetSymbolAddress((void**)&b4, g_buf4);
    cudaGetSymbolAddress((void**)&b5, g_buf5);
    cudaGetSymbolAddress((void**)&b6, g_buf6);
    cudaGetSymbolAddress((void**)&pt, g_part);
    cudaGetSymbolAddress((void**)&f1, g_fc1);
    cudaGetSymbolAddress((void**)&f2, g_fc2);

    const int c1_smem = (2*C1_XSH + 32*C1_KP)*2 + 32*4;
    cudaFuncSetAttribute(conv1_h,
                         cudaFuncAttributeMaxDynamicSharedMemorySize, c1_smem);
    const int reg_smem = (4*RG_CH + 32*RG_KP)*2;
    cudaFuncSetAttribute(region_h,
                         cudaFuncAttributeMaxDynamicSharedMemorySize, reg_smem);
    const int c2_smem = (4240 + 16*C2_KP)*2 + 16*4;
    cudaFuncSetAttribute(conv_nhwc<32,80,80,73,73,1>,
                         cudaFuncAttributeMaxDynamicSharedMemorySize, c2_smem);
    cudaFuncSetAttribute(conv_nhwc<16,73,73,66,66,0>,
                         cudaFuncAttributeMaxDynamicSharedMemorySize, c2_smem);
    const int c4_smem = (8*36*36 + 16*292 + 288 + 16) * 4;
    cudaFuncSetAttribute(conv_tcS<16,6,2,66,66,31,31>,
                         cudaFuncAttributeMaxDynamicSharedMemorySize, c4_smem);
    const int c5_smem = (8*20*20 + 16*204 + 200 + 16) * 4;
    cudaFuncSetAttribute(conv_tcS<16,5,1,31,31,27,27>,
                         cudaFuncAttributeMaxDynamicSharedMemorySize, c5_smem);

    // 1. conv1 -> NHWC half (coalesced epilogue)
    conv1_h<<<dim3(5,10,BATCH), 256, c1_smem>>>(x, conv1_w, conv1_b, b1h);

    // 2. region (coalesced NHWC epilogue)
    region_h<<<BATCH*64, 256, reg_smem>>>(
        b1h, rl_gamma, rl_beta, rl_mean, rl_var, rl_cw, rl_cb,
        bn_gamma, bn_beta, bn_mean, bn_var, b2h);

    // 3. conv2: NHWC -> NHWC (smem-transposed store)
    conv_nhwc<32,80,80,73,73,1><<<dim3(5,5,BATCH), 256, c2_smem>>>(
        b2h, conv2_w, conv2_b, b3h);

    // 4. conv3: NHWC -> NCHW float
    conv_nhwc<16,73,73,66,66,0><<<dim3(5,5,BATCH), 256, c2_smem>>>(
        b3h, conv3_w, conv3_b, b4);

    // 5. conv4
    conv_tcS<16,6,2,66,66,31,31><<<dim3(2,2,BATCH), 256, c4_smem>>>(
        b4, conv4_w, conv4_b, b5);

    // 6. conv5
    conv_tcS<16,5,1,31,31,27,27><<<dim3(2,2,BATCH), 256, c5_smem>>>(
        b5, conv5_w, conv5_b, b6);

    // 7. fc1
    fc_tc<<<dim3(32,24), 256>>>(b6, fc1_w, pt, 4096, 11664, 486);
    fc_reduce<<<512, 256>>>(pt, fc1_b, f1, 4096, 24, 1);

    // 8. fc2
    fc_tc<<<dim3(16,16), 256>>>(f1, fc2_w, pt, 2048, 4096, 256);
    fc_reduce<<<256, 256>>>(pt, fc2_b, f2, 2048, 16, 1);

    // 9. fc3 + log_softmax
    fc3_softmax<<<BATCH, 768>>>(f2, fc3_w, fc3_b, out);
}

// round 13
// speedup vs baseline: 1.3987x; 1.2101x over previous
#include <cuda_runtime.h>
#include <cuda_fp16.h>
#include <cuda_bf16.h>
#include <math.h>
#include <stdint.h>

#define BATCH 32
#define EPS 1e-5f

__device__ __forceinline__ uint32_t f2tf(float f) {
    uint32_t r; asm("cvt.rna.tf32.f32 %0,%1;" : "=r"(r) : "f"(f)); return r;
}
__device__ __forceinline__ void mma8(float* c, uint32_t a0, uint32_t a1,
                                     uint32_t a2, uint32_t a3,
                                     uint32_t b0, uint32_t b1) {
    asm("mma.sync.aligned.m16n8k8.row.col.f32.tf32.tf32.f32 "
        "{%0,%1,%2,%3},{%4,%5,%6,%7},{%8,%9},{%0,%1,%2,%3};"
        : "+f"(c[0]), "+f"(c[1]), "+f"(c[2]), "+f"(c[3])
        : "r"(a0), "r"(a1), "r"(a2), "r"(a3), "r"(b0), "r"(b1));
}
__device__ __forceinline__ void mma16(float* c, uint32_t a0, uint32_t a1,
                                      uint32_t a2, uint32_t a3,
                                      uint32_t b0, uint32_t b1) {
    asm("mma.sync.aligned.m16n8k16.row.col.f32.f16.f16.f32 "
        "{%0,%1,%2,%3},{%4,%5,%6,%7},{%8,%9},{%0,%1,%2,%3};"
        : "+f"(c[0]), "+f"(c[1]), "+f"(c[2]), "+f"(c[3])
        : "r"(a0), "r"(a1), "r"(a2), "r"(a3), "r"(b0), "r"(b1));
}
__device__ __forceinline__ uint32_t s2u(const void* p) {
    return (uint32_t)__cvta_generic_to_shared(p);
}
__device__ __forceinline__ void ldsm4(uint32_t& r0, uint32_t& r1,
                                      uint32_t& r2, uint32_t& r3, uint32_t a) {
    asm volatile("ldmatrix.sync.aligned.m8n8.x4.shared.b16 {%0,%1,%2,%3},[%4];"
        : "=r"(r0), "=r"(r1), "=r"(r2), "=r"(r3) : "r"(a));
}

#define C1_KP 536
#define C1_XSH 4432
#define C2_KP 520
#define RG_CH 3888
#define RG_KP 392

// ---------------- scratch ----------------
__device__ __align__(256) __half g_buf1h[BATCH*160*160*32];  // NHWC
__device__ __align__(256) __half g_buf2h[BATCH*80*80*32];    // NHWC
__device__ __align__(256) __half g_buf3h[BATCH*73*73*16];    // NHWC
__device__ float g_buf4[BATCH*16*66*66];                     // NCHW
__device__ float g_buf5[BATCH*16*31*31];
__device__ float g_buf6[BATCH*16*27*27];
__device__ float g_part[24*32*4096];
__device__ float g_fc1[BATCH*4096];
__device__ float g_fc2[BATCH*2048];
// pre-converted weights (half, padded, k'-reordered)
__device__ __align__(256) __half g_w1h[32*C1_KP];
__device__ __align__(256) __half g_w2h[4*16*C2_KP];
__device__ __align__(256) __half g_w3h[2*16*C2_KP];
__device__ __align__(256) __half g_wrh[64*32*RG_KP];

// =====================================================================
// weight prep kernels
// =====================================================================
__global__ void prep_w1(const float* __restrict__ w, __half* __restrict__ dst)
{
    int i = blockIdx.x*256 + threadIdx.x;
    if (i >= 32*C1_KP) return;
    int oc = i / C1_KP, kl = i - oc*C1_KP;
    float v = 0.f;
    if (kl < 528) {
        int kh = kl / 48, r = kl - kh*48;
        int kw = r >> 2, ic = r & 3;
        if (ic < 3 && kw < 11) v = w[oc*363 + ic*121 + kh*11 + kw];
    }
    dst[i] = __float2half_rn(v);
}

__global__ void prep_w2(const float* __restrict__ w, __half* __restrict__ dst,
                        int CIN)
{
    int i = blockIdx.x*256 + threadIdx.x;
    int total = (CIN/8)*16*C2_KP;
    if (i >= total) return;
    int chunk = i / (16*C2_KP), r = i - chunk*(16*C2_KP);
    int oc = r / C2_KP, kl = r - oc*C2_KP;
    float v = 0.f;
    if (kl < 512) {
        int kh = kl >> 6, kw = (kl >> 3) & 7, ic = kl & 7;
        v = w[((size_t)oc*CIN + chunk*8 + ic)*64 + kh*8 + kw];
    }
    dst[i] = __float2half_rn(v);
}

__global__ void prep_wr(const float* __restrict__ rl_cw, __half* __restrict__ dst)
{
    int i = blockIdx.x*256 + threadIdx.x;
    if (i >= 64*32*RG_KP) return;
    int kidx = i / (32*RG_KP), r = i - kidx*(32*RG_KP);
    int oc = r / RG_KP, kp = r - oc*RG_KP;
    float v = 0.f;
    if (kp < 384) {
        int j = kp >> 4, loc = kp & 15;
        int kxl = loc >> 3, ic8 = loc & 7;
        int c = j / 6, rr = j - c*6;
        int ky = rr >> 1, kx = (rr & 1)*2 + kxl;
        if (kx < 3)
            v = rl_cw[(size_t)kidx*9216 + oc*288 + (c*8 + ic8)*9 + ky*3 + kx];
    }
    dst[i] = __float2half_rn(v);
}

// =====================================================================
// conv1 (fp16 mma + ldmatrix): x NCHW fp32 -> NHWC half
// =====================================================================
__global__ void __launch_bounds__(256) conv1_h(
    const float* __restrict__ x, const __half* __restrict__ wh,
    const float* __restrict__ bias, __half* __restrict__ out)
{
    extern __shared__ __half smh[];
    __half* xs0 = smh;
    __half* xs1 = smh + C1_XSH;
    __half* ws  = smh + 2*C1_XSH;
    float* bs = (float*)(ws + 32*C1_KP);

    const int tid = threadIdx.x, lane = tid & 31, wp = tid >> 5;
    const int b = blockIdx.z;
    const int iy0 = blockIdx.y*16, ix0 = blockIdx.x*32;
    const int gr = lane >> 2, gc = lane & 3;

    if (tid < 4) xs1[4428 + tid] = __float2half_rn(0.f);
    for (int i = tid; i < C1_XSH; i += 256) {
        float v = 0.f;
        if (i < 4368) {
            int p = i >> 2, ic = i & 3;
            int yy = p / 42, xx = p - yy*42;
            if (ic < 3)
                v = x[(((size_t)b*3 + ic)*170 + iy0 + yy)*170 + ix0 + xx];
        }
        __half h = __float2half_rn(v);
        xs0[i] = h;
        if (i >= 4) xs1[i-4] = h;
    }
    for (int i = tid; i < 32*C1_KP/8; i += 256)
        ((uint4*)ws)[i] = ((const uint4*)wh)[i];
    if (tid < 32) bs[tid] = bias[tid];
    __syncthreads();

    float acc[4][4][4];
#pragma unroll
    for (int m = 0; m < 4; m++)
#pragma unroll
        for (int n = 0; n < 4; n++)
#pragma unroll
            for (int q = 0; q < 4; q++) acc[m][n][q] = 0.f;

    const int arow = lane & 15;
    const int acol = (lane >> 4) * 8;
    const int boc  = (lane & 7) | ((lane >> 4) << 3);
    const int bk   = ((lane >> 3) & 1) * 8;
    const uint32_t xsb = s2u(xs0);
    uint32_t aaddr[4];
#pragma unroll
    for (int mt = 0; mt < 4; mt++) {
        int t = wp*4 + mt;
        int py = t >> 1, pxh = (t & 1)*16;
        int q = pxh + arow;
        int par = q & 1;
        aaddr[mt] = xsb + (((py*42 + q - par)*4 + acol)*2) + par*(C1_XSH*2);
    }
    const uint32_t baddr0 = s2u(ws) + (boc*C1_KP + bk)*2;
    const uint32_t baddr1 = baddr0 + 16*C1_KP*2;

    for (int j = 0; j < 33; j++) {
        int kh = j / 3, sub = j - kh*3;
        uint32_t aoff = (kh*42 + sub*4)*8;
        uint32_t c0,c1,c2,c3, d0,d1,d2,d3;
        ldsm4(c0,c1,c2,c3, baddr0 + j*32);
        ldsm4(d0,d1,d2,d3, baddr1 + j*32);
#pragma unroll
        for (int mt = 0; mt < 4; mt++) {
            uint32_t a0,a1,a2,a3;
            ldsm4(a0,a1,a2,a3, aaddr[mt] + aoff);
            mma16(acc[mt][0], a0,a1,a2,a3, c0,c1);
            mma16(acc[mt][1], a0,a1,a2,a3, c2,c3);
            mma16(acc[mt][2], a0,a1,a2,a3, d0,d1);
            mma16(acc[mt][3], a0,a1,a2,a3, d2,d3);
        }
    }
    float bloc[8];
#pragma unroll
    for (int nt = 0; nt < 4; nt++) {
        bloc[2*nt]   = bs[nt*8 + gc*2];
        bloc[2*nt+1] = bs[nt*8 + gc*2 + 1];
    }
    __syncthreads();
    __half* osm = smh;
#pragma unroll
    for (int mt = 0; mt < 4; mt++) {
        int t = wp*4 + mt;
        int p0 = (t >> 1)*32 + (t & 1)*16 + gr;
#pragma unroll
        for (int nt = 0; nt < 4; nt++) {
            int oc = nt*8 + gc*2;
            *(half2*)&osm[p0*36 + oc] = __floats2half2_rn(
                acc[mt][nt][0] + bloc[2*nt], acc[mt][nt][1] + bloc[2*nt+1]);
            *(half2*)&osm[(p0+8)*36 + oc] = __floats2half2_rn(
                acc[mt][nt][2] + bloc[2*nt], acc[mt][nt][3] + bloc[2*nt+1]);
        }
    }
    __syncthreads();
    for (int i = tid; i < 4096; i += 256) {
        int p = i >> 3, seg = i & 7;
        int py = p >> 5, px = p & 31;
        uint2 v = *(uint2*)&osm[p*36 + seg*4];
        *(uint2*)&out[(((size_t)b*160 + iy0 + py)*160 + ix0 + px)*32 + seg*4] = v;
    }
}

// =====================================================================
// region (fp16 mma + ldmatrix): NHWC in/out, pre-converted weights
// =====================================================================
__global__ void __launch_bounds__(256) region_h(
    const __half* __restrict__ in, const __half* __restrict__ wrh,
    const float* __restrict__ rl_gamma, const float* __restrict__ rl_beta,
    const float* __restrict__ rl_mean,  const float* __restrict__ rl_var,
    const float* __restrict__ rl_cb,
    const float* __restrict__ bn_g, const float* __restrict__ bn_b,
    const float* __restrict__ bn_m, const float* __restrict__ bn_v,
    __half* __restrict__ out)
{
    extern __shared__ __half smh[];
    __half* act = smh;                  // 4*3888
    __half* ws  = smh + 4*RG_CH;        // 32*392
    __shared__ float sc[32], sh[32], s2[32], t2[32], cb[32];

    const int blk = blockIdx.x;
    const int b = blk >> 6;
    const int patch = blk & 63;
    const int gi = patch >> 3, gj = patch & 7;
    const int kidx = gj*(gi+1);
    const int tid = threadIdx.x, lane = tid & 31, wp = tid >> 5;
    const int gr = lane >> 2, gc = lane & 3;

    if (tid < 32) {
        float g = rl_gamma[kidx*32+tid];
        float s = g * rsqrtf(rl_var[kidx*32+tid] + EPS);
        sc[tid] = s;
        sh[tid] = rl_beta[kidx*32+tid] - rl_mean[kidx*32+tid]*s;
        float ss = bn_g[tid] * rsqrtf(bn_v[tid] + EPS);
        s2[tid] = ss;
        t2[tid] = bn_b[tid] - bn_m[tid]*ss;
        cb[tid] = rl_cb[kidx*32+tid];
    }
    {
        uint32_t* az = (uint32_t*)act;
        for (int i = tid; i < 2*RG_CH; i += 256) az[i] = 0u;
    }
    // weights: uint4 copy of pre-converted layout
    {
        const uint4* src = (const uint4*)(wrh + (size_t)kidx*32*RG_KP);
        uint4* dst = (uint4*)ws;
        for (int i = tid; i < 32*RG_KP/8; i += 256) dst[i] = src[i];
    }
    __syncthreads();

    const __half* inb = in + (size_t)b*160*160*32;
    for (int i = tid; i < 400*32; i += 256) {
        int pix = i >> 5, ic = i & 31;
        int y = pix / 20, xx = pix - y*20;
        float v = __half2float(inb[((size_t)(gi*20+y)*160 + gj*20+xx)*32 + ic]);
        float a = fmaxf(fmaf(v, sc[ic], sh[ic]), 0.f);
        act[(ic >> 3)*RG_CH + ((y+1)*22 + (xx+1))*8 + (ic & 7)] = __float2half_rn(a);
    }
    __syncthreads();

    const int ntiles = (wp == 0) ? 4 : 3;
    const int arow = lane & 15;
    const int acol = (lane >> 4) * 8;
    const int boc  = (lane & 7) | ((lane >> 4) << 3);
    const int bk   = ((lane >> 3) & 1) * 8;
    uint32_t aaddr[4];
#pragma unroll
    for (int ti = 0; ti < 4; ti++) {
        int t = wp + 8*ti;
        int p = (t < 25) ? t*16 + arow : arow;
        int pixbase = (p/20)*22 + (p%20);
        aaddr[ti] = s2u(act) + (pixbase*8 + acol)*2;
    }
    const uint32_t baddr0 = s2u(ws) + (boc*RG_KP + bk)*2;
    const uint32_t baddr1 = baddr0 + 16*RG_KP*2;

    float acc[4][4][4];
#pragma unroll
    for (int m = 0; m < 4; m++)
#pragma unroll
        for (int n = 0; n < 4; n++)
#pragma unroll
            for (int q = 0; q < 4; q++) acc[m][n][q] = 0.f;

    for (int j = 0; j < 24; j++) {
        int c = j / 6, r = j - c*6;
        int ky = r >> 1, kx0 = (r & 1)*2;
        uint32_t aoff = (c*RG_CH + (ky*22 + kx0)*8)*2;
        uint32_t b0,b1,b2,b3, c0,c1,c2,c3;
        ldsm4(b0,b1,b2,b3, baddr0 + j*32);
        ldsm4(c0,c1,c2,c3, baddr1 + j*32);
#pragma unroll
        for (int ti = 0; ti < 4; ti++) {
            if (ti >= ntiles) break;
            uint32_t a0,a1,a2,a3;
            ldsm4(a0,a1,a2,a3, aaddr[ti] + aoff);
            mma16(acc[ti][0], a0,a1,a2,a3, b0,b1);
            mma16(acc[ti][1], a0,a1,a2,a3, b2,b3);
            mma16(acc[ti][2], a0,a1,a2,a3, c0,c1);
            mma16(acc[ti][3], a0,a1,a2,a3, c2,c3);
        }
    }
    __syncthreads();

    float* res = (float*)smh;          // 32*401 floats
#pragma unroll
    for (int ti = 0; ti < 4; ti++) {
        if (ti >= ntiles) break;
        int t = wp + 8*ti;
        int p0 = t*16 + gr, p1 = p0 + 8;
#pragma unroll
        for (int nt = 0; nt < 4; nt++) {
            int oc0 = nt*8 + 2*gc;
            res[oc0*401 + p0]     = acc[ti][nt][0];
            res[(oc0+1)*401 + p0] = acc[ti][nt][1];
            res[oc0*401 + p1]     = acc[ti][nt][2];
            res[(oc0+1)*401 + p1] = acc[ti][nt][3];
        }
    }
    __syncthreads();

    for (int item = tid; item < 3200; item += 256) {
        int pos = item >> 5, oc = item & 31;
        int py = pos / 10, px = pos - py*10;
        float bv = cb[oc];
        const __half* xrb = inb + ((size_t)(gi*20 + 2*py)*160 + gj*20 + 2*px)*32 + oc;
        int p = (2*py)*20 + 2*px;
        const float* rr = &res[oc*401];
        float v0 = fmaxf(rr[p]      + bv + __half2float(xrb[0]),        0.f);
        float v1 = fmaxf(rr[p + 1]  + bv + __half2float(xrb[32]),       0.f);
        float v2 = fmaxf(rr[p + 20] + bv + __half2float(xrb[160*32]),   0.f);
        float v3 = fmaxf(rr[p + 21] + bv + __half2float(xrb[160*32+32]),0.f);
        float mx = fmaxf(fmaxf(v0, v1), fmaxf(v2, v3));
        out[((size_t)(b*80 + gi*10 + py)*80 + gj*10 + px)*32 + oc] =
            __float2half_rn(fmaf(mx, s2[oc], t2[oc]));
    }
}

// =====================================================================
// conv2/conv3 (fp16 mma + ldmatrix): NHWC in; pre-converted weights
// =====================================================================
template<int CIN, int HIN, int WIN, int HOUT, int WOUT, int OUT_NHWC>
__global__ void __launch_bounds__(256) conv_nhwc(
    const __half* __restrict__ in, const __half* __restrict__ wh,
    const float* __restrict__ bias, void* __restrict__ outv)
{
    extern __shared__ __half smh[];
    __half* xs = smh;                   // 4240
    __half* ws = smh + 4240;            // 16*520
    float* bs = (float*)(ws + 16*C2_KP);

    const int tid = threadIdx.x, lane = tid & 31, wp = tid >> 5;
    const int b = blockIdx.z;
    const int iy0 = blockIdx.y*16, ix0 = blockIdx.x*16;
    const int gr = lane >> 2, gc = lane & 3;

    if (tid < 16) bs[tid] = bias[tid];

    float acc[2][2][4];
#pragma unroll
    for (int m = 0; m < 2; m++)
#pragma unroll
        for (int n = 0; n < 2; n++)
#pragma unroll
            for (int q = 0; q < 4; q++) acc[m][n][q] = 0.f;

    const int arow = lane & 15;
    const int acol = (lane >> 4) * 8;
    const int boc  = (lane & 7) | ((lane >> 4) << 3);
    const int bk   = ((lane >> 3) & 1) * 8;
    uint32_t aaddr[2];
#pragma unroll
    for (int mt = 0; mt < 2; mt++)
        aaddr[mt] = s2u(xs) + (((wp*2 + mt)*23 + arow)*8 + acol)*2;
    const uint32_t baddr = s2u(ws) + (boc*C2_KP + bk)*2;

    for (int cc = 0; cc < CIN; cc += 8) {
        __syncthreads();
        for (int i = tid; i < 529; i += 256) {
            int yy = i / 23, xx = i - yy*23;
            int gy = iy0 + yy, gx = ix0 + xx;
            uint4 v = make_uint4(0u,0u,0u,0u);
            if (gy < HIN && gx < WIN)
                v = *(const uint4*)&in[((size_t)(b*HIN + gy)*WIN + gx)*CIN + cc];
            *(uint4*)&xs[i*8] = v;
        }
        {
            const uint4* src = (const uint4*)(wh + (size_t)(cc >> 3)*16*C2_KP);
            uint4* dst = (uint4*)ws;
            for (int i = tid; i < 16*C2_KP/8; i += 256) dst[i] = src[i];
        }
        __syncthreads();

        for (int j = 0; j < 32; j++) {
            int kh = j >> 2, kw0 = (j & 3)*2;
            uint32_t aoff = (kh*23 + kw0)*16;
            uint32_t b0,b1,b2,b3;
            ldsm4(b0,b1,b2,b3, baddr + j*32);
#pragma unroll
            for (int mt = 0; mt < 2; mt++) {
                uint32_t a0,a1,a2,a3;
                ldsm4(a0,a1,a2,a3, aaddr[mt] + aoff);
                mma16(acc[mt][0], a0,a1,a2,a3, b0,b1);
                mma16(acc[mt][1], a0,a1,a2,a3, b2,b3);
            }
        }
    }

    if (OUT_NHWC) {
        float b0l = bs[gc*2],     b1l = bs[gc*2+1];
        float b2l = bs[8+gc*2],   b3l = bs[8+gc*2+1];
        __syncthreads();
        __half* osm = smh;
#pragma unroll
        for (int mt = 0; mt < 2; mt++) {
            int p0 = (wp*2 + mt)*16 + gr;
            *(half2*)&osm[p0*24 + gc*2] = __floats2half2_rn(
                fmaxf(acc[mt][0][0] + b0l, 0.f), fmaxf(acc[mt][0][1] + b1l, 0.f));
            *(half2*)&osm[p0*24 + 8 + gc*2] = __floats2half2_rn(
                fmaxf(acc[mt][1][0] + b2l, 0.f), fmaxf(acc[mt][1][1] + b3l, 0.f));
            *(half2*)&osm[(p0+8)*24 + gc*2] = __floats2half2_rn(
                fmaxf(acc[mt][0][2] + b0l, 0.f), fmaxf(acc[mt][0][3] + b1l, 0.f));
            *(half2*)&osm[(p0+8)*24 + 8 + gc*2] = __floats2half2_rn(
                fmaxf(acc[mt][1][2] + b2l, 0.f), fmaxf(acc[mt][1][3] + b3l, 0.f));
        }
        __syncthreads();
        __half* o = (__half*)outv;
        for (int i = tid; i < 512; i += 256) {
            int p = i >> 1, seg = i & 1;
            int py = p >> 4, px = p & 15;
            int yp = iy0 + py, xp = ix0 + px;
            if (yp < HOUT && xp < WOUT) {
                uint4 v = *(uint4*)&osm[p*24 + seg*8];
                *(uint4*)&o[((size_t)(b*HOUT + yp)*WOUT + xp)*16 + seg*8] = v;
            }
        }
    } else {
        float* outp = (float*)outv;
        const size_t cstride = (size_t)HOUT*WOUT;
#pragma unroll
        for (int mt = 0; mt < 2; mt++) {
            int yp = iy0 + wp*2 + mt;
            int xp = ix0 + gr;
            if (yp >= HOUT) continue;
#pragma unroll
            for (int nt = 0; nt < 2; nt++) {
                int oc = nt*8 + gc*2;
                float* o0 = outp + (((size_t)b*16 + oc)*HOUT + yp)*WOUT + xp;
                if (xp < WOUT) {
                    o0[0]       = fmaxf(acc[mt][nt][0] + bs[oc],   0.f);
                    o0[cstride] = fmaxf(acc[mt][nt][1] + bs[oc+1], 0.f);
                }
                if (xp + 8 < WOUT) {
                    o0[8]         = fmaxf(acc[mt][nt][2] + bs[oc],   0.f);
                    o0[cstride+8] = fmaxf(acc[mt][nt][3] + bs[oc+1], 0.f);
                }
            }
        }
    }
}

// =====================================================================
// conv4/conv5 (tf32): NCHW float — unchanged
// =====================================================================
template<int CIN, int KS, int STRIDE, int HIN, int WIN, int HOUT, int WOUT>
__global__ void __launch_bounds__(256) conv_tcS(
    const float* __restrict__ in, const float* __restrict__ w,
    const float* __restrict__ bias, float* __restrict__ out)
{
    constexpr int TIW = 15*STRIDE + KS;
    constexpr int KCH = 8*KS*KS;
    constexpr int KP  = KCH + 4;
    extern __shared__ uint32_t sm_u[];
    uint32_t* xs = sm_u;
    uint32_t* ws = xs + 8*TIW*TIW;
    int* lut = (int*)(ws + 16*KP);
    float* bs = (float*)(lut + KCH);

    const int tid = threadIdx.x, lane = tid & 31, wp = tid >> 5;
    const int b = blockIdx.z;
    const int iy0in = blockIdx.y*16*STRIDE, ix0in = blockIdx.x*16*STRIDE;

    for (int i = tid; i < KCH; i += 256) {
        int cl = i / (KS*KS), r = i - cl*(KS*KS);
        lut[i] = cl*(TIW*TIW) + (r/KS)*TIW + (r%KS);
    }
    if (tid < 16) bs[tid] = bias[tid];

    float acc[2][2][4];
#pragma unroll
    for (int m = 0; m < 2; m++)
#pragma unroll
        for (int n = 0; n < 2; n++)
#pragma unroll
            for (int q = 0; q < 4; q++) acc[m][n][q] = 0.f;

    const int gr = lane >> 2, gc = lane & 3;
    int mb[2];
#pragma unroll
    for (int i = 0; i < 2; i++)
        mb[i] = (STRIDE*(wp*2 + i))*TIW + STRIDE*gr;
    const int a1off = 8*STRIDE;

    for (int cc = 0; cc < CIN; cc += 8) {
        __syncthreads();
        for (int i = tid; i < 8*TIW*TIW; i += 256) {
            int cl = i / (TIW*TIW), r = i - cl*(TIW*TIW);
            int yy = r / TIW, xx = r - yy*TIW;
            int gy = iy0in + yy, gx = ix0in + xx;
            float v = 0.f;
            if (gy < HIN && gx < WIN)
                v = in[(((size_t)b*CIN + cc + cl)*HIN + gy)*WIN + gx];
            xs[i] = f2tf(v);
        }
        for (int i = tid; i < 16*KCH; i += 256) {
            int oc = i / KCH, kl = i - oc*KCH;
            int cl = kl / (KS*KS), kk = kl - cl*(KS*KS);
            ws[oc*KP + kl] = f2tf(w[((size_t)oc*CIN + cc + cl)*(KS*KS) + kk]);
        }
        __syncthreads();

        for (int k0 = 0; k0 < KCH; k0 += 8) {
            int o1 = lut[k0 + gc], o2 = lut[k0 + gc + 4];
            uint32_t bf0[2], bf1[2];
#pragma unroll
            for (int nt = 0; nt < 2; nt++) {
                const uint32_t* wp_ = &ws[(nt*8 + gr)*KP + k0];
                bf0[nt] = wp_[gc]; bf1[nt] = wp_[gc + 4];
            }
#pragma unroll
            for (int mt = 0; mt < 2; mt++) {
                uint32_t a0 = xs[mb[mt] + o1], a1 = xs[mb[mt] + a1off + o1];
                uint32_t a2 = xs[mb[mt] + o2], a3 = xs[mb[mt] + a1off + o2];
#pragma unroll
                for (int nt = 0; nt < 2; nt++)
                    mma8(acc[mt][nt], a0, a1, a2, a3, bf0[nt], bf1[nt]);
            }
        }
    }

    const size_t cstride = (size_t)HOUT*WOUT;
#pragma unroll
    for (int mt = 0; mt < 2; mt++) {
        int yp = blockIdx.y*16 + wp*2 + mt;
        int xp = blockIdx.x*16 + gr;
        if (yp < HOUT) {
#pragma unroll
            for (int nt = 0; nt < 2; nt++) {
                int oc = nt*8 + gc*2;
                float* o0 = out + (((size_t)b*16 + oc)*HOUT + yp)*WOUT + xp;
                if (xp < WOUT) {
                    o0[0]       = fmaxf(acc[mt][nt][0] + bs[oc],   0.f);
                    o0[cstride] = fmaxf(acc[mt][nt][1] + bs[oc+1], 0.f);
                }
                if (xp + 8 < WOUT) {
                    o0[8]         = fmaxf(acc[mt][nt][2] + bs[oc],   0.f);
                    o0[cstride+8] = fmaxf(acc[mt][nt][3] + bs[oc+1], 0.f);
                }
            }
        }
    }
}

// =====================================================================
// fc (tf32) — unchanged
// =====================================================================
__global__ void __launch_bounds__(256) fc_tc(
    const float* __restrict__ x, const float* __restrict__ w,
    float* __restrict__ part, int N, int K, int klen)
{
    __shared__ uint32_t as[32*68];
    __shared__ uint32_t bsm[128*68];

    const int tid = threadIdx.x, lane = tid & 31, wp = tid >> 5;
    const int n0 = blockIdx.x*128;
    const int kstart = blockIdx.y*klen;
    const int gr = lane >> 2, gc = lane & 3;
    const int nb = wp*16;

    float acc[2][2][4];
#pragma unroll
    for (int m = 0; m < 2; m++)
#pragma unroll
        for (int n = 0; n < 2; n++)
#pragma unroll
            for (int q = 0; q < 4; q++) acc[m][n][q] = 0.f;

    for (int kc = 0; kc < klen; kc += 64) {
        int cl = min(64, klen - kc);
        __syncthreads();
        for (int i = tid; i < 2048; i += 256) {
            int m = i >> 6, k = i & 63;
            float v = (k < cl) ? x[(size_t)m*K + kstart + kc + k] : 0.f;
            as[m*68 + k] = f2tf(v);
        }
        for (int i = tid; i < 8192; i += 256) {
            int n = i >> 6, k = i & 63;
            float v = (k < cl) ? w[(size_t)(n0 + n)*K + kstart + kc + k] : 0.f;
            bsm[n*68 + k] = f2tf(v);
        }
        __syncthreads();

#pragma unroll
        for (int k0 = 0; k0 < 64; k0 += 8) {
            uint32_t a0[2], a1[2], a2[2], a3[2];
#pragma unroll
            for (int mt = 0; mt < 2; mt++) {
                const uint32_t* ap = &as[(mt*16 + gr)*68 + k0];
                a0[mt] = ap[gc];        a2[mt] = ap[gc + 4];
                a1[mt] = ap[8*68 + gc]; a3[mt] = ap[8*68 + gc + 4];
            }
#pragma unroll
            for (int nt = 0; nt < 2; nt++) {
                const uint32_t* bp = &bsm[(nb + nt*8 + gr)*68 + k0];
                uint32_t b0 = bp[gc], b1 = bp[gc + 4];
#pragma unroll
                for (int mt = 0; mt < 2; mt++)
                    mma8(acc[mt][nt], a0[mt], a1[mt], a2[mt], a3[mt], b0, b1);
            }
        }
    }

    float* pr = part + (size_t)blockIdx.y*32*N;
#pragma unroll
    for (int mt = 0; mt < 2; mt++) {
#pragma unroll
        for (int nt = 0; nt < 2; nt++) {
            int n = n0 + nb + nt*8 + 2*gc;
            int m0 = mt*16 + gr;
            *(float2*)&pr[(size_t)m0*N + n]     = make_float2(acc[mt][nt][0], acc[mt][nt][1]);
            *(float2*)&pr[(size_t)(m0+8)*N + n] = make_float2(acc[mt][nt][2], acc[mt][nt][3]);
        }
    }
}

__global__ void fc_reduce(const float* __restrict__ part,
                          const float* __restrict__ bias,
                          float* __restrict__ out, int N, int KT, int do_relu)
{
    int i = blockIdx.x*256 + threadIdx.x;
    if (i >= 32*N) return;
    int n = i % N;
    float s = bias[n];
    for (int kt = 0; kt < KT; kt++) s += part[(size_t)kt*32*N + i];
    out[i] = do_relu ? fmaxf(s, 0.f) : s;
}

__global__ void __launch_bounds__(768) fc3_softmax(
    const float* __restrict__ x, const float* __restrict__ w,
    const float* __restrict__ bias, float* __restrict__ out)
{
    __shared__ float lg[24];
    const int b = blockIdx.x;
    const int tid = threadIdx.x;
    const int wo = tid >> 5, lane = tid & 31;

    const float* xr = x + (size_t)b*2048;
    const float* wr = w + (size_t)wo*2048;
    float s = 0.f;
    for (int k = lane; k < 2048; k += 32) s = fmaf(wr[k], xr[k], s);
#pragma unroll
    for (int off = 16; off; off >>= 1) s += __shfl_xor_sync(0xffffffffu, s, off);
    if (lane == 0) lg[wo] = s + bias[wo];
    __syncthreads();

    if (tid < 24) {
        int a = tid % 12;
        float z0 = lg[a], z1 = lg[12 + a];
        float m = fmaxf(z0, z1);
        float lse = m + logf(expf(z0 - m) + expf(z1 - m));
        out[b*24 + tid] = lg[tid] - lse;
    }
}

// =====================================================================
// launch
// =====================================================================
extern "C" void kernel_launch(void* const* d_in, const int* in_sizes, int n_in,
                              void* d_out, int out_size)
{
    const float* x        = (const float*)d_in[0];
    const float* conv1_w  = (const float*)d_in[1];
    const float* conv1_b  = (const float*)d_in[2];
    const float* rl_gamma = (const float*)d_in[3];
    const float* rl_beta  = (const float*)d_in[4];
    const float* rl_mean  = (const float*)d_in[5];
    const float* rl_var   = (const float*)d_in[6];
    const float* rl_cw    = (const float*)d_in[7];
    const float* rl_cb    = (const float*)d_in[8];
    const float* bn_gamma = (const float*)d_in[9];
    const float* bn_beta  = (const float*)d_in[10];
    const float* bn_mean  = (const float*)d_in[11];
    const float* bn_var   = (const float*)d_in[12];
    const float* conv2_w  = (const float*)d_in[13];
    const float* conv2_b  = (const float*)d_in[14];
    const float* conv3_w  = (const float*)d_in[15];
    const float* conv3_b  = (const float*)d_in[16];
    const float* conv4_w  = (const float*)d_in[17];
    const float* conv4_b  = (const float*)d_in[18];
    const float* conv5_w  = (const float*)d_in[19];
    const float* conv5_b  = (const float*)d_in[20];
    const float* fc1_w    = (const float*)d_in[21];
    const float* fc1_b    = (const float*)d_in[22];
    const float* fc2_w    = (const float*)d_in[23];
    const float* fc2_b    = (const float*)d_in[24];
    const float* fc3_w    = (const float*)d_in[25];
    const float* fc3_b    = (const float*)d_in[26];
    float* out = (float*)d_out;

    __half *b1h, *b2h, *b3h, *w1h, *w2h, *w3h, *wrh;
    float *b4,*b5,*b6,*pt,*f1,*f2;
    cudaGetSymbolAddress((void**)&b1h, g_buf1h);
    cudaGetSymbolAddress((void**)&b2h, g_buf2h);
    cudaGetSymbolAddress((void**)&b3h, g_buf3h);
    cudaGetSymbolAddress((void**)&b4, g_buf4);
    cudaGetSymbolAddress((void**)&b5, g_buf5);
    cudaGetSymbolAddress((void**)&b6, g_buf6);
    cudaGetSymbolAddress((void**)&pt, g_part);
    cudaGetSymbolAddress((void**)&f1, g_fc1);
    cudaGetSymbolAddress((void**)&f2, g_fc2);
    cudaGetSymbolAddress((void**)&w1h, g_w1h);
    cudaGetSymbolAddress((void**)&w2h, g_w2h);
    cudaGetSymbolAddress((void**)&w3h, g_w3h);
    cudaGetSymbolAddress((void**)&wrh, g_wrh);

    const int c1_smem = (2*C1_XSH + 32*C1_KP)*2 + 32*4;
    cudaFuncSetAttribute(conv1_h,
                         cudaFuncAttributeMaxDynamicSharedMemorySize, c1_smem);
    const int reg_smem = (4*RG_CH + 32*RG_KP)*2;
    cudaFuncSetAttribute(region_h,
                         cudaFuncAttributeMaxDynamicSharedMemorySize, reg_smem);
    const int c2_smem = (4240 + 16*C2_KP)*2 + 16*4;
    cudaFuncSetAttribute(conv_nhwc<32,80,80,73,73,1>,
                         cudaFuncAttributeMaxDynamicSharedMemorySize, c2_smem);
    cudaFuncSetAttribute(conv_nhwc<16,73,73,66,66,0>,
                         cudaFuncAttributeMaxDynamicSharedMemorySize, c2_smem);
    const int c4_smem = (8*36*36 + 16*292 + 288 + 16) * 4;
    cudaFuncSetAttribute(conv_tcS<16,6,2,66,66,31,31>,
                         cudaFuncAttributeMaxDynamicSharedMemorySize, c4_smem);
    const int c5_smem = (8*20*20 + 16*204 + 200 + 16) * 4;
    cudaFuncSetAttribute(conv_tcS<16,5,1,31,31,27,27>,
                         cudaFuncAttributeMaxDynamicSharedMemorySize, c5_smem);

    // 0. weight prep (tiny)
    prep_w1<<<(32*C1_KP + 255)/256, 256>>>(conv1_w, w1h);
    prep_w2<<<(4*16*C2_KP + 255)/256, 256>>>(conv2_w, w2h, 32);
    prep_w2<<<(2*16*C2_KP + 255)/256, 256>>>(conv3_w, w3h, 16);
    prep_wr<<<(64*32*RG_KP + 255)/256, 256>>>(rl_cw, wrh);

    // 1. conv1
    conv1_h<<<dim3(5,10,BATCH), 256, c1_smem>>>(x, w1h, conv1_b, b1h);

    // 2. region
    region_h<<<BATCH*64, 256, reg_smem>>>(
        b1h, wrh, rl_gamma, rl_beta, rl_mean, rl_var, rl_cb,
        bn_gamma, bn_beta, bn_mean, bn_var, b2h);

    // 3. conv2
    conv_nhwc<32,80,80,73,73,1><<<dim3(5,5,BATCH), 256, c2_smem>>>(
        b2h, w2h, conv2_b, b3h);

    // 4. conv3
    conv_nhwc<16,73,73,66,66,0><<<dim3(5,5,BATCH), 256, c2_smem>>>(
        b3h, w3h, conv3_b, b4);

    // 5. conv4
    conv_tcS<16,6,2,66,66,31,31><<<dim3(2,2,BATCH), 256, c4_smem>>>(
        b4, conv4_w, conv4_b, b5);

    // 6. conv5
    conv_tcS<16,5,1,31,31,27,27><<<dim3(2,2,BATCH), 256, c5_smem>>>(
        b5, conv5_w, conv5_b, b6);

    // 7. fc1
    fc_tc<<<dim3(32,24), 256>>>(b6, fc1_w, pt, 4096, 11664, 486);
    fc_reduce<<<512, 256>>>(pt, fc1_b, f1, 4096, 24, 1);

    // 8. fc2
    fc_tc<<<dim3(16,16), 256>>>(f1, fc2_w, pt, 2048, 4096, 256);
    fc_reduce<<<256, 256>>>(pt, fc2_b, f2, 2048, 16, 1);

    // 9. fc3 + log_softmax
    fc3_softmax<<<BATCH, 768>>>(f2, fc3_w, fc3_b, out);
}

// round 14
// speedup vs baseline: 1.6380x; 1.1711x over previous
#include <cuda_runtime.h>
#include <cuda_fp16.h>
#include <cuda_bf16.h>
#include <math.h>
#include <stdint.h>

#define BATCH 32
#define EPS 1e-5f

__device__ __forceinline__ uint32_t f2tf(float f) {
    uint32_t r; asm("cvt.rna.tf32.f32 %0,%1;" : "=r"(r) : "f"(f)); return r;
}
__device__ __forceinline__ void mma8(float* c, uint32_t a0, uint32_t a1,
                                     uint32_t a2, uint32_t a3,
                                     uint32_t b0, uint32_t b1) {
    asm("mma.sync.aligned.m16n8k8.row.col.f32.tf32.tf32.f32 "
        "{%0,%1,%2,%3},{%4,%5,%6,%7},{%8,%9},{%0,%1,%2,%3};"
        : "+f"(c[0]), "+f"(c[1]), "+f"(c[2]), "+f"(c[3])
        : "r"(a0), "r"(a1), "r"(a2), "r"(a3), "r"(b0), "r"(b1));
}
__device__ __forceinline__ void mma16(float* c, uint32_t a0, uint32_t a1,
                                      uint32_t a2, uint32_t a3,
                                      uint32_t b0, uint32_t b1) {
    asm("mma.sync.aligned.m16n8k16.row.col.f32.f16.f16.f32 "
        "{%0,%1,%2,%3},{%4,%5,%6,%7},{%8,%9},{%0,%1,%2,%3};"
        : "+f"(c[0]), "+f"(c[1]), "+f"(c[2]), "+f"(c[3])
        : "r"(a0), "r"(a1), "r"(a2), "r"(a3), "r"(b0), "r"(b1));
}
__device__ __forceinline__ uint32_t s2u(const void* p) {
    return (uint32_t)__cvta_generic_to_shared(p);
}
__device__ __forceinline__ void ldsm4(uint32_t& r0, uint32_t& r1,
                                      uint32_t& r2, uint32_t& r3, uint32_t a) {
    asm volatile("ldmatrix.sync.aligned.m8n8.x4.shared.b16 {%0,%1,%2,%3},[%4];"
        : "=r"(r0), "=r"(r1), "=r"(r2), "=r"(r3) : "r"(a));
}

#define C1_KP 536
#define C1_XSH 4432
#define C2_KP 520
#define RG_CH 3888
#define RG_KP 392

// ---------------- scratch ----------------
__device__ __align__(256) __half g_buf1h[BATCH*160*160*32];  // NHWC
__device__ __align__(256) __half g_buf2h[BATCH*80*80*32];    // NHWC
__device__ __align__(256) __half g_buf3h[BATCH*73*73*16];    // NHWC
__device__ float g_buf4[BATCH*16*66*66];                     // NCHW
__device__ float g_buf5[BATCH*16*31*31];
__device__ float g_buf6[BATCH*16*27*27];
__device__ float g_part[24*32*4096];
__device__ float g_fc1[BATCH*4096];
__device__ float g_fc2[BATCH*2048];
// pre-converted weights
__device__ __align__(256) __half g_w1h[32*C1_KP];
__device__ __align__(256) __half g_w2h[4*16*C2_KP];
__device__ __align__(256) __half g_w3h[2*16*C2_KP];
__device__ __align__(256) __half g_wrh[64*32*RG_KP];

// =====================================================================
// weight prep kernels
// =====================================================================
__global__ void prep_w1(const float* __restrict__ w, __half* __restrict__ dst)
{
    int i = blockIdx.x*256 + threadIdx.x;
    if (i >= 32*C1_KP) return;
    int oc = i / C1_KP, kl = i - oc*C1_KP;
    float v = 0.f;
    if (kl < 528) {
        int kh = kl / 48, r = kl - kh*48;
        int kw = r >> 2, ic = r & 3;
        if (ic < 3 && kw < 11) v = w[oc*363 + ic*121 + kh*11 + kw];
    }
    dst[i] = __float2half_rn(v);
}

__global__ void prep_w2(const float* __restrict__ w, __half* __restrict__ dst,
                        int CIN)
{
    int i = blockIdx.x*256 + threadIdx.x;
    int total = (CIN/8)*16*C2_KP;
    if (i >= total) return;
    int chunk = i / (16*C2_KP), r = i - chunk*(16*C2_KP);
    int oc = r / C2_KP, kl = r - oc*C2_KP;
    float v = 0.f;
    if (kl < 512) {
        int kh = kl >> 6, kw = (kl >> 3) & 7, ic = kl & 7;
        v = w[((size_t)oc*CIN + chunk*8 + ic)*64 + kh*8 + kw];
    }
    dst[i] = __float2half_rn(v);
}

__global__ void prep_wr(const float* __restrict__ rl_cw, __half* __restrict__ dst)
{
    int i = blockIdx.x*256 + threadIdx.x;
    if (i >= 64*32*RG_KP) return;
    int kidx = i / (32*RG_KP), r = i - kidx*(32*RG_KP);
    int oc = r / RG_KP, kp = r - oc*RG_KP;
    float v = 0.f;
    if (kp < 384) {
        int j = kp >> 4, loc = kp & 15;
        int kxl = loc >> 3, ic8 = loc & 7;
        int c = j / 6, rr = j - c*6;
        int ky = rr >> 1, kx = (rr & 1)*2 + kxl;
        if (kx < 3)
            v = rl_cw[(size_t)kidx*9216 + oc*288 + (c*8 + ic8)*9 + ky*3 + kx];
    }
    dst[i] = __float2half_rn(v);
}

// =====================================================================
// conv1 (fp16 mma + ldmatrix)
// =====================================================================
__global__ void __launch_bounds__(256) conv1_h(
    const float* __restrict__ x, const __half* __restrict__ wh,
    const float* __restrict__ bias, __half* __restrict__ out)
{
    extern __shared__ __half smh[];
    __half* xs0 = smh;
    __half* xs1 = smh + C1_XSH;
    __half* ws  = smh + 2*C1_XSH;
    float* bs = (float*)(ws + 32*C1_KP);

    const int tid = threadIdx.x, lane = tid & 31, wp = tid >> 5;
    const int b = blockIdx.z;
    const int iy0 = blockIdx.y*16, ix0 = blockIdx.x*32;
    const int gr = lane >> 2, gc = lane & 3;

    if (tid < 4) xs1[4428 + tid] = __float2half_rn(0.f);
    for (int i = tid; i < C1_XSH; i += 256) {
        float v = 0.f;
        if (i < 4368) {
            int p = i >> 2, ic = i & 3;
            int yy = p / 42, xx = p - yy*42;
            if (ic < 3)
                v = x[(((size_t)b*3 + ic)*170 + iy0 + yy)*170 + ix0 + xx];
        }
        __half h = __float2half_rn(v);
        xs0[i] = h;
        if (i >= 4) xs1[i-4] = h;
    }
    for (int i = tid; i < 32*C1_KP/8; i += 256)
        ((uint4*)ws)[i] = ((const uint4*)wh)[i];
    if (tid < 32) bs[tid] = bias[tid];
    __syncthreads();

    float acc[4][4][4];
#pragma unroll
    for (int m = 0; m < 4; m++)
#pragma unroll
        for (int n = 0; n < 4; n++)
#pragma unroll
            for (int q = 0; q < 4; q++) acc[m][n][q] = 0.f;

    const int arow = lane & 15;
    const int acol = (lane >> 4) * 8;
    const int boc  = (lane & 7) | ((lane >> 4) << 3);
    const int bk   = ((lane >> 3) & 1) * 8;
    const uint32_t xsb = s2u(xs0);
    uint32_t aaddr[4];
#pragma unroll
    for (int mt = 0; mt < 4; mt++) {
        int t = wp*4 + mt;
        int py = t >> 1, pxh = (t & 1)*16;
        int q = pxh + arow;
        int par = q & 1;
        aaddr[mt] = xsb + (((py*42 + q - par)*4 + acol)*2) + par*(C1_XSH*2);
    }
    const uint32_t baddr0 = s2u(ws) + (boc*C1_KP + bk)*2;
    const uint32_t baddr1 = baddr0 + 16*C1_KP*2;

    for (int j = 0; j < 33; j++) {
        int kh = j / 3, sub = j - kh*3;
        uint32_t aoff = (kh*42 + sub*4)*8;
        uint32_t c0,c1,c2,c3, d0,d1,d2,d3;
        ldsm4(c0,c1,c2,c3, baddr0 + j*32);
        ldsm4(d0,d1,d2,d3, baddr1 + j*32);
#pragma unroll
        for (int mt = 0; mt < 4; mt++) {
            uint32_t a0,a1,a2,a3;
            ldsm4(a0,a1,a2,a3, aaddr[mt] + aoff);
            mma16(acc[mt][0], a0,a1,a2,a3, c0,c1);
            mma16(acc[mt][1], a0,a1,a2,a3, c2,c3);
            mma16(acc[mt][2], a0,a1,a2,a3, d0,d1);
            mma16(acc[mt][3], a0,a1,a2,a3, d2,d3);
        }
    }
    float bloc[8];
#pragma unroll
    for (int nt = 0; nt < 4; nt++) {
        bloc[2*nt]   = bs[nt*8 + gc*2];
        bloc[2*nt+1] = bs[nt*8 + gc*2 + 1];
    }
    __syncthreads();
    __half* osm = smh;
#pragma unroll
    for (int mt = 0; mt < 4; mt++) {
        int t = wp*4 + mt;
        int p0 = (t >> 1)*32 + (t & 1)*16 + gr;
#pragma unroll
        for (int nt = 0; nt < 4; nt++) {
            int oc = nt*8 + gc*2;
            *(half2*)&osm[p0*36 + oc] = __floats2half2_rn(
                acc[mt][nt][0] + bloc[2*nt], acc[mt][nt][1] + bloc[2*nt+1]);
            *(half2*)&osm[(p0+8)*36 + oc] = __floats2half2_rn(
                acc[mt][nt][2] + bloc[2*nt], acc[mt][nt][3] + bloc[2*nt+1]);
        }
    }
    __syncthreads();
    for (int i = tid; i < 4096; i += 256) {
        int p = i >> 3, seg = i & 7;
        int py = p >> 5, px = p & 31;
        uint2 v = *(uint2*)&osm[p*36 + seg*4];
        *(uint2*)&out[(((size_t)b*160 + iy0 + py)*160 + ix0 + px)*32 + seg*4] = v;
    }
}

// =====================================================================
// region (fp16 mma + ldmatrix): vectorized act staging
// =====================================================================
__global__ void __launch_bounds__(256) region_h(
    const __half* __restrict__ in, const __half* __restrict__ wrh,
    const float* __restrict__ rl_gamma, const float* __restrict__ rl_beta,
    const float* __restrict__ rl_mean,  const float* __restrict__ rl_var,
    const float* __restrict__ rl_cb,
    const float* __restrict__ bn_g, const float* __restrict__ bn_b,
    const float* __restrict__ bn_m, const float* __restrict__ bn_v,
    __half* __restrict__ out)
{
    extern __shared__ __half smh[];
    __half* act = smh;                  // 4*3888
    __half* ws  = smh + 4*RG_CH;        // 32*392
    __shared__ float sc[32], sh[32], s2[32], t2[32], cb[32];

    const int blk = blockIdx.x;
    const int b = blk >> 6;
    const int patch = blk & 63;
    const int gi = patch >> 3, gj = patch & 7;
    const int kidx = gj*(gi+1);
    const int tid = threadIdx.x, lane = tid & 31, wp = tid >> 5;
    const int gr = lane >> 2, gc = lane & 3;

    if (tid < 32) {
        float g = rl_gamma[kidx*32+tid];
        float s = g * rsqrtf(rl_var[kidx*32+tid] + EPS);
        sc[tid] = s;
        sh[tid] = rl_beta[kidx*32+tid] - rl_mean[kidx*32+tid]*s;
        float ss = bn_g[tid] * rsqrtf(bn_v[tid] + EPS);
        s2[tid] = ss;
        t2[tid] = bn_b[tid] - bn_m[tid]*ss;
        cb[tid] = rl_cb[kidx*32+tid];
    }
    {
        uint32_t* az = (uint32_t*)act;
        for (int i = tid; i < 2*RG_CH; i += 256) az[i] = 0u;
    }
    {
        const uint4* src = (const uint4*)(wrh + (size_t)kidx*32*RG_KP);
        uint4* dst = (uint4*)ws;
        for (int i = tid; i < 32*RG_KP/8; i += 256) dst[i] = src[i];
    }
    __syncthreads();

    const __half* inb = in + (size_t)b*160*160*32;
    // vectorized act staging: 1600 uint4 items (400 px x 4 ic8-chunks)
    for (int i = tid; i < 1600; i += 256) {
        int pix = i >> 2, c = i & 3;
        int y = pix / 20, xx = pix - y*20;
        uint4 v = *(const uint4*)&inb[((size_t)(gi*20+y)*160 + gj*20+xx)*32 + c*8];
        __half h[8]; *(uint4*)h = v;
        __half o[8];
#pragma unroll
        for (int k = 0; k < 8; k++) {
            float f = __half2float(h[k]);
            o[k] = __float2half_rn(fmaxf(fmaf(f, sc[c*8+k], sh[c*8+k]), 0.f));
        }
        *(uint4*)&act[c*RG_CH + ((y+1)*22 + (xx+1))*8] = *(uint4*)o;
    }
    __syncthreads();

    const int ntiles = (wp == 0) ? 4 : 3;
    const int arow = lane & 15;
    const int acol = (lane >> 4) * 8;
    const int boc  = (lane & 7) | ((lane >> 4) << 3);
    const int bk   = ((lane >> 3) & 1) * 8;
    uint32_t aaddr[4];
#pragma unroll
    for (int ti = 0; ti < 4; ti++) {
        int t = wp + 8*ti;
        int p = (t < 25) ? t*16 + arow : arow;
        int pixbase = (p/20)*22 + (p%20);
        aaddr[ti] = s2u(act) + (pixbase*8 + acol)*2;
    }
    const uint32_t baddr0 = s2u(ws) + (boc*RG_KP + bk)*2;
    const uint32_t baddr1 = baddr0 + 16*RG_KP*2;

    float acc[4][4][4];
#pragma unroll
    for (int m = 0; m < 4; m++)
#pragma unroll
        for (int n = 0; n < 4; n++)
#pragma unroll
            for (int q = 0; q < 4; q++) acc[m][n][q] = 0.f;

    for (int j = 0; j < 24; j++) {
        int c = j / 6, r = j - c*6;
        int ky = r >> 1, kx0 = (r & 1)*2;
        uint32_t aoff = (c*RG_CH + (ky*22 + kx0)*8)*2;
        uint32_t b0,b1,b2,b3, c0,c1,c2,c3;
        ldsm4(b0,b1,b2,b3, baddr0 + j*32);
        ldsm4(c0,c1,c2,c3, baddr1 + j*32);
#pragma unroll
        for (int ti = 0; ti < 4; ti++) {
            if (ti >= ntiles) break;
            uint32_t a0,a1,a2,a3;
            ldsm4(a0,a1,a2,a3, aaddr[ti] + aoff);
            mma16(acc[ti][0], a0,a1,a2,a3, b0,b1);
            mma16(acc[ti][1], a0,a1,a2,a3, b2,b3);
            mma16(acc[ti][2], a0,a1,a2,a3, c0,c1);
            mma16(acc[ti][3], a0,a1,a2,a3, c2,c3);
        }
    }
    __syncthreads();

    float* res = (float*)smh;          // 32*401 floats
#pragma unroll
    for (int ti = 0; ti < 4; ti++) {
        if (ti >= ntiles) break;
        int t = wp + 8*ti;
        int p0 = t*16 + gr, p1 = p0 + 8;
#pragma unroll
        for (int nt = 0; nt < 4; nt++) {
            int oc0 = nt*8 + 2*gc;
            res[oc0*401 + p0]     = acc[ti][nt][0];
            res[(oc0+1)*401 + p0] = acc[ti][nt][1];
            res[oc0*401 + p1]     = acc[ti][nt][2];
            res[(oc0+1)*401 + p1] = acc[ti][nt][3];
        }
    }
    __syncthreads();

    for (int item = tid; item < 3200; item += 256) {
        int pos = item >> 5, oc = item & 31;
        int py = pos / 10, px = pos - py*10;
        float bv = cb[oc];
        const __half* xrb = inb + ((size_t)(gi*20 + 2*py)*160 + gj*20 + 2*px)*32 + oc;
        int p = (2*py)*20 + 2*px;
        const float* rr = &res[oc*401];
        float v0 = fmaxf(rr[p]      + bv + __half2float(xrb[0]),        0.f);
        float v1 = fmaxf(rr[p + 1]  + bv + __half2float(xrb[32]),       0.f);
        float v2 = fmaxf(rr[p + 20] + bv + __half2float(xrb[160*32]),   0.f);
        float v3 = fmaxf(rr[p + 21] + bv + __half2float(xrb[160*32+32]),0.f);
        float mx = fmaxf(fmaxf(v0, v1), fmaxf(v2, v3));
        out[((size_t)(b*80 + gi*10 + py)*80 + gj*10 + px)*32 + oc] =
            __float2half_rn(fmaf(mx, s2[oc], t2[oc]));
    }
}

// =====================================================================
// conv2/conv3 (fp16 mma + ldmatrix): NHWC in; PRELOAD hoists weights
// =====================================================================
template<int CIN, int HIN, int WIN, int HOUT, int WOUT, int OUT_NHWC, int PRELOAD>
__global__ void __launch_bounds__(256) conv_nhwc(
    const __half* __restrict__ in, const __half* __restrict__ wh,
    const float* __restrict__ bias, void* __restrict__ outv)
{
    constexpr int NCH = CIN/8;
    constexpr int WCH = PRELOAD ? NCH : 1;
    extern __shared__ __half smh[];
    __half* xs = smh;                   // 4240
    __half* ws = smh + 4240;            // WCH*16*520
    float* bs = (float*)(ws + WCH*16*C2_KP);

    const int tid = threadIdx.x, lane = tid & 31, wp = tid >> 5;
    const int b = blockIdx.z;
    const int iy0 = blockIdx.y*16, ix0 = blockIdx.x*16;
    const int gr = lane >> 2, gc = lane & 3;

    if (tid < 16) bs[tid] = bias[tid];
    if (PRELOAD) {
        const uint4* src = (const uint4*)wh;
        uint4* dst = (uint4*)ws;
        for (int i = tid; i < WCH*16*C2_KP/8; i += 256) dst[i] = src[i];
    }

    float acc[2][2][4];
#pragma unroll
    for (int m = 0; m < 2; m++)
#pragma unroll
        for (int n = 0; n < 2; n++)
#pragma unroll
            for (int q = 0; q < 4; q++) acc[m][n][q] = 0.f;

    const int arow = lane & 15;
    const int acol = (lane >> 4) * 8;
    const int boc  = (lane & 7) | ((lane >> 4) << 3);
    const int bk   = ((lane >> 3) & 1) * 8;
    uint32_t aaddr[2];
#pragma unroll
    for (int mt = 0; mt < 2; mt++)
        aaddr[mt] = s2u(xs) + (((wp*2 + mt)*23 + arow)*8 + acol)*2;
    const uint32_t baddr_base = s2u(ws) + (boc*C2_KP + bk)*2;

    for (int cc = 0; cc < CIN; cc += 8) {
        __syncthreads();
        for (int i = tid; i < 529; i += 256) {
            int yy = i / 23, xx = i - yy*23;
            int gy = iy0 + yy, gx = ix0 + xx;
            uint4 v = make_uint4(0u,0u,0u,0u);
            if (gy < HIN && gx < WIN)
                v = *(const uint4*)&in[((size_t)(b*HIN + gy)*WIN + gx)*CIN + cc];
            *(uint4*)&xs[i*8] = v;
        }
        if (!PRELOAD) {
            const uint4* src = (const uint4*)(wh + (size_t)(cc >> 3)*16*C2_KP);
            uint4* dst = (uint4*)ws;
            for (int i = tid; i < 16*C2_KP/8; i += 256) dst[i] = src[i];
        }
        __syncthreads();

        const uint32_t baddr = PRELOAD ? baddr_base + (cc >> 3)*16*C2_KP*2
                                       : baddr_base;
        for (int j = 0; j < 32; j++) {
            int kh = j >> 2, kw0 = (j & 3)*2;
            uint32_t aoff = (kh*23 + kw0)*16;
            uint32_t b0,b1,b2,b3;
            ldsm4(b0,b1,b2,b3, baddr + j*32);
#pragma unroll
            for (int mt = 0; mt < 2; mt++) {
                uint32_t a0,a1,a2,a3;
                ldsm4(a0,a1,a2,a3, aaddr[mt] + aoff);
                mma16(acc[mt][0], a0,a1,a2,a3, b0,b1);
                mma16(acc[mt][1], a0,a1,a2,a3, b2,b3);
            }
        }
    }

    if (OUT_NHWC) {
        float b0l = bs[gc*2],     b1l = bs[gc*2+1];
        float b2l = bs[8+gc*2],   b3l = bs[8+gc*2+1];
        __syncthreads();
        __half* osm = smh;
#pragma unroll
        for (int mt = 0; mt < 2; mt++) {
            int p0 = (wp*2 + mt)*16 + gr;
            *(half2*)&osm[p0*24 + gc*2] = __floats2half2_rn(
                fmaxf(acc[mt][0][0] + b0l, 0.f), fmaxf(acc[mt][0][1] + b1l, 0.f));
            *(half2*)&osm[p0*24 + 8 + gc*2] = __floats2half2_rn(
                fmaxf(acc[mt][1][0] + b2l, 0.f), fmaxf(acc[mt][1][1] + b3l, 0.f));
            *(half2*)&osm[(p0+8)*24 + gc*2] = __floats2half2_rn(
                fmaxf(acc[mt][0][2] + b0l, 0.f), fmaxf(acc[mt][0][3] + b1l, 0.f));
            *(half2*)&osm[(p0+8)*24 + 8 + gc*2] = __floats2half2_rn(
                fmaxf(acc[mt][1][2] + b2l, 0.f), fmaxf(acc[mt][1][3] + b3l, 0.f));
        }
        __syncthreads();
        __half* o = (__half*)outv;
        for (int i = tid; i < 512; i += 256) {
            int p = i >> 1, seg = i & 1;
            int py = p >> 4, px = p & 15;
            int yp = iy0 + py, xp = ix0 + px;
            if (yp < HOUT && xp < WOUT) {
                uint4 v = *(uint4*)&osm[p*24 + seg*8];
                *(uint4*)&o[((size_t)(b*HOUT + yp)*WOUT + xp)*16 + seg*8] = v;
            }
        }
    } else {
        float* outp = (float*)outv;
        const size_t cstride = (size_t)HOUT*WOUT;
#pragma unroll
        for (int mt = 0; mt < 2; mt++) {
            int yp = iy0 + wp*2 + mt;
            int xp = ix0 + gr;
            if (yp >= HOUT) continue;
#pragma unroll
            for (int nt = 0; nt < 2; nt++) {
                int oc = nt*8 + gc*2;
                float* o0 = outp + (((size_t)b*16 + oc)*HOUT + yp)*WOUT + xp;
                if (xp < WOUT) {
                    o0[0]       = fmaxf(acc[mt][nt][0] + bs[oc],   0.f);
                    o0[cstride] = fmaxf(acc[mt][nt][1] + bs[oc+1], 0.f);
                }
                if (xp + 8 < WOUT) {
                    o0[8]         = fmaxf(acc[mt][nt][2] + bs[oc],   0.f);
                    o0[cstride+8] = fmaxf(acc[mt][nt][3] + bs[oc+1], 0.f);
                }
            }
        }
    }
}

// =====================================================================
// conv4/conv5 (tf32): NCHW float — unchanged
// =====================================================================
template<int CIN, int KS, int STRIDE, int HIN, int WIN, int HOUT, int WOUT>
__global__ void __launch_bounds__(256) conv_tcS(
    const float* __restrict__ in, const float* __restrict__ w,
    const float* __restrict__ bias, float* __restrict__ out)
{
    constexpr int TIW = 15*STRIDE + KS;
    constexpr int KCH = 8*KS*KS;
    constexpr int KP  = KCH + 4;
    extern __shared__ uint32_t sm_u[];
    uint32_t* xs = sm_u;
    uint32_t* ws = xs + 8*TIW*TIW;
    int* lut = (int*)(ws + 16*KP);
    float* bs = (float*)(lut + KCH);

    const int tid = threadIdx.x, lane = tid & 31, wp = tid >> 5;
    const int b = blockIdx.z;
    const int iy0in = blockIdx.y*16*STRIDE, ix0in = blockIdx.x*16*STRIDE;

    for (int i = tid; i < KCH; i += 256) {
        int cl = i / (KS*KS), r = i - cl*(KS*KS);
        lut[i] = cl*(TIW*TIW) + (r/KS)*TIW + (r%KS);
    }
    if (tid < 16) bs[tid] = bias[tid];

    float acc[2][2][4];
#pragma unroll
    for (int m = 0; m < 2; m++)
#pragma unroll
        for (int n = 0; n < 2; n++)
#pragma unroll
            for (int q = 0; q < 4; q++) acc[m][n][q] = 0.f;

    const int gr = lane >> 2, gc = lane & 3;
    int mb[2];
#pragma unroll
    for (int i = 0; i < 2; i++)
        mb[i] = (STRIDE*(wp*2 + i))*TIW + STRIDE*gr;
    const int a1off = 8*STRIDE;

    for (int cc = 0; cc < CIN; cc += 8) {
        __syncthreads();
        for (int i = tid; i < 8*TIW*TIW; i += 256) {
            int cl = i / (TIW*TIW), r = i - cl*(TIW*TIW);
            int yy = r / TIW, xx = r - yy*TIW;
            int gy = iy0in + yy, gx = ix0in + xx;
            float v = 0.f;
            if (gy < HIN && gx < WIN)
                v = in[(((size_t)b*CIN + cc + cl)*HIN + gy)*WIN + gx];
            xs[i] = f2tf(v);
        }
        for (int i = tid; i < 16*KCH; i += 256) {
            int oc = i / KCH, kl = i - oc*KCH;
            int cl = kl / (KS*KS), kk = kl - cl*(KS*KS);
            ws[oc*KP + kl] = f2tf(w[((size_t)oc*CIN + cc + cl)*(KS*KS) + kk]);
        }
        __syncthreads();

        for (int k0 = 0; k0 < KCH; k0 += 8) {
            int o1 = lut[k0 + gc], o2 = lut[k0 + gc + 4];
            uint32_t bf0[2], bf1[2];
#pragma unroll
            for (int nt = 0; nt < 2; nt++) {
                const uint32_t* wp_ = &ws[(nt*8 + gr)*KP + k0];
                bf0[nt] = wp_[gc]; bf1[nt] = wp_[gc + 4];
            }
#pragma unroll
            for (int mt = 0; mt < 2; mt++) {
                uint32_t a0 = xs[mb[mt] + o1], a1 = xs[mb[mt] + a1off + o1];
                uint32_t a2 = xs[mb[mt] + o2], a3 = xs[mb[mt] + a1off + o2];
#pragma unroll
                for (int nt = 0; nt < 2; nt++)
                    mma8(acc[mt][nt], a0, a1, a2, a3, bf0[nt], bf1[nt]);
            }
        }
    }

    const size_t cstride = (size_t)HOUT*WOUT;
#pragma unroll
    for (int mt = 0; mt < 2; mt++) {
        int yp = blockIdx.y*16 + wp*2 + mt;
        int xp = blockIdx.x*16 + gr;
        if (yp < HOUT) {
#pragma unroll
            for (int nt = 0; nt < 2; nt++) {
                int oc = nt*8 + gc*2;
                float* o0 = out + (((size_t)b*16 + oc)*HOUT + yp)*WOUT + xp;
                if (xp < WOUT) {
                    o0[0]       = fmaxf(acc[mt][nt][0] + bs[oc],   0.f);
                    o0[cstride] = fmaxf(acc[mt][nt][1] + bs[oc+1], 0.f);
                }
                if (xp + 8 < WOUT) {
                    o0[8]         = fmaxf(acc[mt][nt][2] + bs[oc],   0.f);
                    o0[cstride+8] = fmaxf(acc[mt][nt][3] + bs[oc+1], 0.f);
                }
            }
        }
    }
}

// =====================================================================
// fc (tf32): vectorized float2 staging
// =====================================================================
__global__ void __launch_bounds__(256) fc_tc(
    const float* __restrict__ x, const float* __restrict__ w,
    float* __restrict__ part, int N, int K, int klen)
{
    __shared__ uint32_t as[32*68];
    __shared__ uint32_t bsm[128*68];

    const int tid = threadIdx.x, lane = tid & 31, wp = tid >> 5;
    const int n0 = blockIdx.x*128;
    const int kstart = blockIdx.y*klen;
    const int gr = lane >> 2, gc = lane & 3;
    const int nb = wp*16;

    float acc[2][2][4];
#pragma unroll
    for (int m = 0; m < 2; m++)
#pragma unroll
        for (int n = 0; n < 2; n++)
#pragma unroll
            for (int q = 0; q < 4; q++) acc[m][n][q] = 0.f;

    for (int kc = 0; kc < klen; kc += 64) {
        int cl = min(64, klen - kc);     // even
        __syncthreads();
        for (int i = tid; i < 1024; i += 256) {   // 32 m x 32 k-pairs
            int m = i >> 5, k2 = i & 31;
            int k = k2*2;
            float2 v = make_float2(0.f, 0.f);
            if (k < cl)
                v = *(const float2*)&x[(size_t)m*K + kstart + kc + k];
            as[m*68 + k]     = f2tf(v.x);
            as[m*68 + k + 1] = f2tf(v.y);
        }
        for (int i = tid; i < 4096; i += 256) {   // 128 n x 32 k-pairs
            int n = i >> 5, k2 = i & 31;
            int k = k2*2;
            float2 v = make_float2(0.f, 0.f);
            if (k < cl)
                v = *(const float2*)&w[(size_t)(n0 + n)*K + kstart + kc + k];
            bsm[n*68 + k]     = f2tf(v.x);
            bsm[n*68 + k + 1] = f2tf(v.y);
        }
        __syncthreads();

#pragma unroll
        for (int k0 = 0; k0 < 64; k0 += 8) {
            uint32_t a0[2], a1[2], a2[2], a3[2];
#pragma unroll
            for (int mt = 0; mt < 2; mt++) {
                const uint32_t* ap = &as[(mt*16 + gr)*68 + k0];
                a0[mt] = ap[gc];        a2[mt] = ap[gc + 4];
                a1[mt] = ap[8*68 + gc]; a3[mt] = ap[8*68 + gc + 4];
            }
#pragma unroll
            for (int nt = 0; nt < 2; nt++) {
                const uint32_t* bp = &bsm[(nb + nt*8 + gr)*68 + k0];
                uint32_t b0 = bp[gc], b1 = bp[gc + 4];
#pragma unroll
                for (int mt = 0; mt < 2; mt++)
                    mma8(acc[mt][nt], a0[mt], a1[mt], a2[mt], a3[mt], b0, b1);
            }
        }
    }

    float* pr = part + (size_t)blockIdx.y*32*N;
#pragma unroll
    for (int mt = 0; mt < 2; mt++) {
#pragma unroll
        for (int nt = 0; nt < 2; nt++) {
            int n = n0 + nb + nt*8 + 2*gc;
            int m0 = mt*16 + gr;
            *(float2*)&pr[(size_t)m0*N + n]     = make_float2(acc[mt][nt][0], acc[mt][nt][1]);
            *(float2*)&pr[(size_t)(m0+8)*N + n] = make_float2(acc[mt][nt][2], acc[mt][nt][3]);
        }
    }
}

__global__ void fc_reduce(const float* __restrict__ part,
                          const float* __restrict__ bias,
                          float* __restrict__ out, int N, int KT, int do_relu)
{
    int i = blockIdx.x*256 + threadIdx.x;
    if (i >= 32*N) return;
    int n = i % N;
    float s = bias[n];
    for (int kt = 0; kt < KT; kt++) s += part[(size_t)kt*32*N + i];
    out[i] = do_relu ? fmaxf(s, 0.f) : s;
}

__global__ void __launch_bounds__(768) fc3_softmax(
    const float* __restrict__ x, const float* __restrict__ w,
    const float* __restrict__ bias, float* __restrict__ out)
{
    __shared__ float lg[24];
    const int b = blockIdx.x;
    const int tid = threadIdx.x;
    const int wo = tid >> 5, lane = tid & 31;

    const float* xr = x + (size_t)b*2048;
    const float* wr = w + (size_t)wo*2048;
    float s = 0.f;
    for (int k = lane; k < 2048; k += 32) s = fmaf(wr[k], xr[k], s);
#pragma unroll
    for (int off = 16; off; off >>= 1) s += __shfl_xor_sync(0xffffffffu, s, off);
    if (lane == 0) lg[wo] = s + bias[wo];
    __syncthreads();

    if (tid < 24) {
        int a = tid % 12;
        float z0 = lg[a], z1 = lg[12 + a];
        float m = fmaxf(z0, z1);
        float lse = m + logf(expf(z0 - m) + expf(z1 - m));
        out[b*24 + tid] = lg[tid] - lse;
    }
}

// =====================================================================
// launch
// =====================================================================
extern "C" void kernel_launch(void* const* d_in, const int* in_sizes, int n_in,
                              void* d_out, int out_size)
{
    const float* x        = (const float*)d_in[0];
    const float* conv1_w  = (const float*)d_in[1];
    const float* conv1_b  = (const float*)d_in[2];
    const float* rl_gamma = (const float*)d_in[3];
    const float* rl_beta  = (const float*)d_in[4];
    const float* rl_mean  = (const float*)d_in[5];
    const float* rl_var   = (const float*)d_in[6];
    const float* rl_cw    = (const float*)d_in[7];
    const float* rl_cb    = (const float*)d_in[8];
    const float* bn_gamma = (const float*)d_in[9];
    const float* bn_beta  = (const float*)d_in[10];
    const float* bn_mean  = (const float*)d_in[11];
    const float* bn_var   = (const float*)d_in[12];
    const float* conv2_w  = (const float*)d_in[13];
    const float* conv2_b  = (const float*)d_in[14];
    const float* conv3_w  = (const float*)d_in[15];
    const float* conv3_b  = (const float*)d_in[16];
    const float* conv4_w  = (const float*)d_in[17];
    const float* conv4_b  = (const float*)d_in[18];
    const float* conv5_w  = (const float*)d_in[19];
    const float* conv5_b  = (const float*)d_in[20];
    const float* fc1_w    = (const float*)d_in[21];
    const float* fc1_b    = (const float*)d_in[22];
    const float* fc2_w    = (const float*)d_in[23];
    const float* fc2_b    = (const float*)d_in[24];
    const float* fc3_w    = (const float*)d_in[25];
    const float* fc3_b    = (const float*)d_in[26];
    float* out = (float*)d_out;

    __half *b1h, *b2h, *b3h, *w1h, *w2h, *w3h, *wrh;
    float *b4,*b5,*b6,*pt,*f1,*f2;
    cudaGetSymbolAddress((void**)&b1h, g_buf1h);
    cudaGetSymbolAddress((void**)&b2h, g_buf2h);
    cudaGetSymbolAddress((void**)&b3h, g_buf3h);
    cudaGetSymbolAddress((void**)&b4, g_buf4);
    cudaGetSymbolAddress((void**)&b5, g_buf5);
    cudaGetSymbolAddress((void**)&b6, g_buf6);
    cudaGetSymbolAddress((void**)&pt, g_part);
    cudaGetSymbolAddress((void**)&f1, g_fc1);
    cudaGetSymbolAddress((void**)&f2, g_fc2);
    cudaGetSymbolAddress((void**)&w1h, g_w1h);
    cudaGetSymbolAddress((void**)&w2h, g_w2h);
    cudaGetSymbolAddress((void**)&w3h, g_w3h);
    cudaGetSymbolAddress((void**)&wrh, g_wrh);

    const int c1_smem = (2*C1_XSH + 32*C1_KP)*2 + 32*4;
    cudaFuncSetAttribute(conv1_h,
                         cudaFuncAttributeMaxDynamicSharedMemorySize, c1_smem);
    const int reg_smem = (4*RG_CH + 32*RG_KP)*2;
    cudaFuncSetAttribute(region_h,
                         cudaFuncAttributeMaxDynamicSharedMemorySize, reg_smem);
    const int c2_smem = (4240 + 16*C2_KP)*2 + 16*4;
    cudaFuncSetAttribute((const void*)conv_nhwc<32,80,80,73,73,1,0>,
                         cudaFuncAttributeMaxDynamicSharedMemorySize, c2_smem);
    const int c3_smem = (4240 + 2*16*C2_KP)*2 + 16*4;
    cudaFuncSetAttribute((const void*)conv_nhwc<16,73,73,66,66,0,1>,
                         cudaFuncAttributeMaxDynamicSharedMemorySize, c3_smem);
    const int c4_smem = (8*36*36 + 16*292 + 288 + 16) * 4;
    cudaFuncSetAttribute(conv_tcS<16,6,2,66,66,31,31>,
                         cudaFuncAttributeMaxDynamicSharedMemorySize, c4_smem);
    const int c5_smem = (8*20*20 + 16*204 + 200 + 16) * 4;
    cudaFuncSetAttribute(conv_tcS<16,5,1,31,31,27,27>,
                         cudaFuncAttributeMaxDynamicSharedMemorySize, c5_smem);

    // 0. weight prep
    prep_w1<<<(32*C1_KP + 255)/256, 256>>>(conv1_w, w1h);
    prep_w2<<<(4*16*C2_KP + 255)/256, 256>>>(conv2_w, w2h, 32);
    prep_w2<<<(2*16*C2_KP + 255)/256, 256>>>(conv3_w, w3h, 16);
    prep_wr<<<(64*32*RG_KP + 255)/256, 256>>>(rl_cw, wrh);

    // 1. conv1
    conv1_h<<<dim3(5,10,BATCH), 256, c1_smem>>>(x, w1h, conv1_b, b1h);

    // 2. region
    region_h<<<BATCH*64, 256, reg_smem>>>(
        b1h, wrh, rl_gamma, rl_beta, rl_mean, rl_var, rl_cb,
        bn_gamma, bn_beta, bn_mean, bn_var, b2h);

    // 3. conv2
    conv_nhwc<32,80,80,73,73,1,0><<<dim3(5,5,BATCH), 256, c2_smem>>>(
        b2h, w2h, conv2_b, b3h);

    // 4. conv3 (weights preloaded)
    conv_nhwc<16,73,73,66,66,0,1><<<dim3(5,5,BATCH), 256, c3_smem>>>(
        b3h, w3h, conv3_b, b4);

    // 5. conv4
    conv_tcS<16,6,2,66,66,31,31><<<dim3(2,2,BATCH), 256, c4_smem>>>(
        b4, conv4_w, conv4_b, b5);

    // 6. conv5
    conv_tcS<16,5,1,31,31,27,27><<<dim3(2,2,BATCH), 256, c5_smem>>>(
        b5, conv5_w, conv5_b, b6);

    // 7. fc1
    fc_tc<<<dim3(32,24), 256>>>(b6, fc1_w, pt, 4096, 11664, 486);
    fc_reduce<<<512, 256>>>(pt, fc1_b, f1, 4096, 24, 1);

    // 8. fc2
    fc_tc<<<dim3(16,16), 256>>>(f1, fc2_w, pt, 2048, 4096, 256);
    fc_reduce<<<256, 256>>>(pt, fc2_b, f2, 2048, 16, 1);

    // 9. fc3 + log_softmax
    fc3_softmax<<<BATCH, 768>>>(f2, fc3_w, fc3_b, out);
}

// round 16
// speedup vs baseline: 1.7364x; 1.0601x over previous
#include <cuda_runtime.h>
#include <cuda_fp16.h>
#include <cuda_bf16.h>
#include <math.h>
#include <stdint.h>

#define BATCH 32
#define EPS 1e-5f

__device__ __forceinline__ uint32_t f2tf(float f) {
    uint32_t r; asm("cvt.rna.tf32.f32 %0,%1;" : "=r"(r) : "f"(f)); return r;
}
__device__ __forceinline__ void mma8(float* c, uint32_t a0, uint32_t a1,
                                     uint32_t a2, uint32_t a3,
                                     uint32_t b0, uint32_t b1) {
    asm("mma.sync.aligned.m16n8k8.row.col.f32.tf32.tf32.f32 "
        "{%0,%1,%2,%3},{%4,%5,%6,%7},{%8,%9},{%0,%1,%2,%3};"
        : "+f"(c[0]), "+f"(c[1]), "+f"(c[2]), "+f"(c[3])
        : "r"(a0), "r"(a1), "r"(a2), "r"(a3), "r"(b0), "r"(b1));
}
__device__ __forceinline__ void mma16(float* c, uint32_t a0, uint32_t a1,
                                      uint32_t a2, uint32_t a3,
                                      uint32_t b0, uint32_t b1) {
    asm("mma.sync.aligned.m16n8k16.row.col.f32.f16.f16.f32 "
        "{%0,%1,%2,%3},{%4,%5,%6,%7},{%8,%9},{%0,%1,%2,%3};"
        : "+f"(c[0]), "+f"(c[1]), "+f"(c[2]), "+f"(c[3])
        : "r"(a0), "r"(a1), "r"(a2), "r"(a3), "r"(b0), "r"(b1));
}
__device__ __forceinline__ uint32_t s2u(const void* p) {
    return (uint32_t)__cvta_generic_to_shared(p);
}
__device__ __forceinline__ void ldsm4(uint32_t& r0, uint32_t& r1,
                                      uint32_t& r2, uint32_t& r3, uint32_t a) {
    asm volatile("ldmatrix.sync.aligned.m8n8.x4.shared.b16 {%0,%1,%2,%3},[%4];"
        : "=r"(r0), "=r"(r1), "=r"(r2), "=r"(r3) : "r"(a));
}

#define C1_KP 536
#define C1_XSH 4432
#define C2_KP 520
#define RG_CH 3888
#define RG_KP 392

// ---------------- scratch ----------------
__device__ __align__(256) __half g_xh[BATCH*170*170*4];      // input NHWC4 half
__device__ __align__(256) __half g_buf1h[BATCH*160*160*32];  // NHWC
__device__ __align__(256) __half g_buf2h[BATCH*80*80*32];    // NHWC
__device__ __align__(256) __half g_buf3h[BATCH*73*73*16];    // NHWC
__device__ float g_buf4[BATCH*16*66*66];                     // NCHW
__device__ float g_buf5[BATCH*16*31*31];
__device__ float g_buf6[BATCH*16*27*27];
__device__ float g_part[24*32*4096];
__device__ float g_fc1[BATCH*4096];
__device__ float g_fc2[BATCH*2048];
// pre-converted weights
__device__ __align__(256) __half g_w1h[32*C1_KP];
__device__ __align__(256) __half g_w2h[4*16*C2_KP];
__device__ __align__(256) __half g_w3h[2*16*C2_KP];
__device__ __align__(256) __half g_wrh[64*32*RG_KP];

// =====================================================================
// prep kernels
// =====================================================================
__global__ void prep_x(const float* __restrict__ x, __half* __restrict__ xh)
{
    int i = blockIdx.x*256 + threadIdx.x;   // pixel index
    if (i >= BATCH*170*170) return;
    int b = i / 28900, p = i - b*28900;
    const float* xb = x + (size_t)b*3*28900 + p;
    __half o[4];
    o[0] = __float2half_rn(xb[0]);
    o[1] = __float2half_rn(xb[28900]);
    o[2] = __float2half_rn(xb[2*28900]);
    o[3] = __float2half_rn(0.f);
    *(uint2*)&xh[(size_t)i*4] = *(uint2*)o;
}

__global__ void prep_w1(const float* __restrict__ w, __half* __restrict__ dst)
{
    int i = blockIdx.x*256 + threadIdx.x;
    if (i >= 32*C1_KP) return;
    int oc = i / C1_KP, kl = i - oc*C1_KP;
    float v = 0.f;
    if (kl < 528) {
        int kh = kl / 48, r = kl - kh*48;
        int kw = r >> 2, ic = r & 3;
        if (ic < 3 && kw < 11) v = w[oc*363 + ic*121 + kh*11 + kw];
    }
    dst[i] = __float2half_rn(v);
}

__global__ void prep_w2(const float* __restrict__ w, __half* __restrict__ dst,
                        int CIN)
{
    int i = blockIdx.x*256 + threadIdx.x;
    int total = (CIN/8)*16*C2_KP;
    if (i >= total) return;
    int chunk = i / (16*C2_KP), r = i - chunk*(16*C2_KP);
    int oc = r / C2_KP, kl = r - oc*C2_KP;
    float v = 0.f;
    if (kl < 512) {
        int kh = kl >> 6, kw = (kl >> 3) & 7, ic = kl & 7;
        v = w[((size_t)oc*CIN + chunk*8 + ic)*64 + kh*8 + kw];
    }
    dst[i] = __float2half_rn(v);
}

__global__ void prep_wr(const float* __restrict__ rl_cw, __half* __restrict__ dst)
{
    int i = blockIdx.x*256 + threadIdx.x;
    if (i >= 64*32*RG_KP) return;
    int kidx = i / (32*RG_KP), r = i - kidx*(32*RG_KP);
    int oc = r / RG_KP, kp = r - oc*RG_KP;
    float v = 0.f;
    if (kp < 384) {
        int j = kp >> 4, loc = kp & 15;
        int kxl = loc >> 3, ic8 = loc & 7;
        int c = j / 6, rr = j - c*6;
        int ky = rr >> 1, kx = (rr & 1)*2 + kxl;
        if (kx < 3)
            v = rl_cw[(size_t)kidx*9216 + oc*288 + (c*8 + ic8)*9 + ky*3 + kx];
    }
    dst[i] = __float2half_rn(v);
}

// =====================================================================
// conv1 (fp16 mma + ldmatrix): xh NHWC4 half -> NHWC half out
// =====================================================================
__global__ void __launch_bounds__(256) conv1_h(
    const __half* __restrict__ xh, const __half* __restrict__ wh,
    const float* __restrict__ bias, __half* __restrict__ out)
{
    extern __shared__ __half smh[];
    __half* xs0 = smh;
    __half* xs1 = smh + C1_XSH;
    __half* ws  = smh + 2*C1_XSH;
    float* bs = (float*)(ws + 32*C1_KP);

    const int tid = threadIdx.x, lane = tid & 31, wp = tid >> 5;
    const int b = blockIdx.z;
    const int iy0 = blockIdx.y*16, ix0 = blockIdx.x*32;
    const int gr = lane >> 2, gc = lane & 3;

    // vectorized staging: one uint2 (4 halves) per pixel; xs1 = shift by 1 px
    if (tid == 0) *(uint2*)&xs1[1107*4] = make_uint2(0u, 0u);
    for (int i = tid; i < 1108; i += 256) {
        uint2 v = make_uint2(0u, 0u);
        if (i < 1092) {
            int yy = i / 42, xx = i - yy*42;
            v = *(const uint2*)&xh[(((size_t)b*170 + iy0 + yy)*170 + ix0 + xx)*4];
        }
        *(uint2*)&xs0[i*4] = v;
        if (i) *(uint2*)&xs1[(i-1)*4] = v;
    }
    for (int i = tid; i < 32*C1_KP/8; i += 256)
        ((uint4*)ws)[i] = ((const uint4*)wh)[i];
    if (tid < 32) bs[tid] = bias[tid];
    __syncthreads();

    float acc[4][4][4];
#pragma unroll
    for (int m = 0; m < 4; m++)
#pragma unroll
        for (int n = 0; n < 4; n++)
#pragma unroll
            for (int q = 0; q < 4; q++) acc[m][n][q] = 0.f;

    const int arow = lane & 15;
    const int acol = (lane >> 4) * 8;
    const int boc  = (lane & 7) | ((lane >> 4) << 3);
    const int bk   = ((lane >> 3) & 1) * 8;
    const uint32_t xsb = s2u(xs0);
    uint32_t aaddr[4];
#pragma unroll
    for (int mt = 0; mt < 4; mt++) {
        int t = wp*4 + mt;
        int py = t >> 1, pxh = (t & 1)*16;
        int q = pxh + arow;
        int par = q & 1;
        aaddr[mt] = xsb + (((py*42 + q - par)*4 + acol)*2) + par*(C1_XSH*2);
    }
    const uint32_t baddr0 = s2u(ws) + (boc*C1_KP + bk)*2;
    const uint32_t baddr1 = baddr0 + 16*C1_KP*2;

    for (int j = 0; j < 33; j++) {
        int kh = j / 3, sub = j - kh*3;
        uint32_t aoff = (kh*42 + sub*4)*8;
        uint32_t c0,c1,c2,c3, d0,d1,d2,d3;
        ldsm4(c0,c1,c2,c3, baddr0 + j*32);
        ldsm4(d0,d1,d2,d3, baddr1 + j*32);
#pragma unroll
        for (int mt = 0; mt < 4; mt++) {
            uint32_t a0,a1,a2,a3;
            ldsm4(a0,a1,a2,a3, aaddr[mt] + aoff);
            mma16(acc[mt][0], a0,a1,a2,a3, c0,c1);
            mma16(acc[mt][1], a0,a1,a2,a3, c2,c3);
            mma16(acc[mt][2], a0,a1,a2,a3, d0,d1);
            mma16(acc[mt][3], a0,a1,a2,a3, d2,d3);
        }
    }
    float bloc[8];
#pragma unroll
    for (int nt = 0; nt < 4; nt++) {
        bloc[2*nt]   = bs[nt*8 + gc*2];
        bloc[2*nt+1] = bs[nt*8 + gc*2 + 1];
    }
    __syncthreads();
    __half* osm = smh;
#pragma unroll
    for (int mt = 0; mt < 4; mt++) {
        int t = wp*4 + mt;
        int p0 = (t >> 1)*32 + (t & 1)*16 + gr;
#pragma unroll
        for (int nt = 0; nt < 4; nt++) {
            int oc = nt*8 + gc*2;
            *(half2*)&osm[p0*36 + oc] = __floats2half2_rn(
                acc[mt][nt][0] + bloc[2*nt], acc[mt][nt][1] + bloc[2*nt+1]);
            *(half2*)&osm[(p0+8)*36 + oc] = __floats2half2_rn(
                acc[mt][nt][2] + bloc[2*nt], acc[mt][nt][3] + bloc[2*nt+1]);
        }
    }
    __syncthreads();
    for (int i = tid; i < 4096; i += 256) {
        int p = i >> 3, seg = i & 7;
        int py = p >> 5, px = p & 31;
        uint2 v = *(uint2*)&osm[p*36 + seg*4];
        *(uint2*)&out[(((size_t)b*160 + iy0 + py)*160 + ix0 + px)*32 + seg*4] = v;
    }
}

// =====================================================================
// region (fp16 mma + ldmatrix)
// =====================================================================
__global__ void __launch_bounds__(256) region_h(
    const __half* __restrict__ in, const __half* __restrict__ wrh,
    const float* __restrict__ rl_gamma, const float* __restrict__ rl_beta,
    const float* __restrict__ rl_mean,  const float* __restrict__ rl_var,
    const float* __restrict__ rl_cb,
    const float* __restrict__ bn_g, const float* __restrict__ bn_b,
    const float* __restrict__ bn_m, const float* __restrict__ bn_v,
    __half* __restrict__ out)
{
    extern __shared__ __half smh[];
    __half* act = smh;                  // 4*3888
    __half* ws  = smh + 4*RG_CH;        // 32*392
    __shared__ float sc[32], sh[32], s2[32], t2[32], cb[32];

    const int blk = blockIdx.x;
    const int b = blk >> 6;
    const int patch = blk & 63;
    const int gi = patch >> 3, gj = patch & 7;
    const int kidx = gj*(gi+1);
    const int tid = threadIdx.x, lane = tid & 31, wp = tid >> 5;
    const int gr = lane >> 2, gc = lane & 3;

    if (tid < 32) {
        float g = rl_gamma[kidx*32+tid];
        float s = g * rsqrtf(rl_var[kidx*32+tid] + EPS);
        sc[tid] = s;
        sh[tid] = rl_beta[kidx*32+tid] - rl_mean[kidx*32+tid]*s;
        float ss = bn_g[tid] * rsqrtf(bn_v[tid] + EPS);
        s2[tid] = ss;
        t2[tid] = bn_b[tid] - bn_m[tid]*ss;
        cb[tid] = rl_cb[kidx*32+tid];
    }
    {
        uint4* az = (uint4*)act;
        uint4 z = make_uint4(0u,0u,0u,0u);
        for (int i = tid; i < RG_CH/2; i += 256) az[i] = z;
    }
    {
        const uint4* src = (const uint4*)(wrh + (size_t)kidx*32*RG_KP);
        uint4* dst = (uint4*)ws;
        for (int i = tid; i < 32*RG_KP/8; i += 256) dst[i] = src[i];
    }
    __syncthreads();

    const __half* inb = in + (size_t)b*160*160*32;
    for (int i = tid; i < 1600; i += 256) {
        int pix = i >> 2, c = i & 3;
        int y = pix / 20, xx = pix - y*20;
        uint4 v = *(const uint4*)&inb[((size_t)(gi*20+y)*160 + gj*20+xx)*32 + c*8];
        __half h[8]; *(uint4*)h = v;
        __half o[8];
#pragma unroll
        for (int k = 0; k < 8; k++) {
            float f = __half2float(h[k]);
            o[k] = __float2half_rn(fmaxf(fmaf(f, sc[c*8+k], sh[c*8+k]), 0.f));
        }
        *(uint4*)&act[c*RG_CH + ((y+1)*22 + (xx+1))*8] = *(uint4*)o;
    }
    __syncthreads();

    const int ntiles = (wp == 0) ? 4 : 3;
    const int arow = lane & 15;
    const int acol = (lane >> 4) * 8;
    const int boc  = (lane & 7) | ((lane >> 4) << 3);
    const int bk   = ((lane >> 3) & 1) * 8;
    uint32_t aaddr[4];
#pragma unroll
    for (int ti = 0; ti < 4; ti++) {
        int t = wp + 8*ti;
        int p = (t < 25) ? t*16 + arow : arow;
        int pixbase = (p/20)*22 + (p%20);
        aaddr[ti] = s2u(act) + (pixbase*8 + acol)*2;
    }
    const uint32_t baddr0 = s2u(ws) + (boc*RG_KP + bk)*2;
    const uint32_t baddr1 = baddr0 + 16*RG_KP*2;

    float acc[4][4][4];
#pragma unroll
    for (int m = 0; m < 4; m++)
#pragma unroll
        for (int n = 0; n < 4; n++)
#pragma unroll
            for (int q = 0; q < 4; q++) acc[m][n][q] = 0.f;

    for (int j = 0; j < 24; j++) {
        int c = j / 6, r = j - c*6;
        int ky = r >> 1, kx0 = (r & 1)*2;
        uint32_t aoff = (c*RG_CH + (ky*22 + kx0)*8)*2;
        uint32_t b0,b1,b2,b3, c0,c1,c2,c3;
        ldsm4(b0,b1,b2,b3, baddr0 + j*32);
        ldsm4(c0,c1,c2,c3, baddr1 + j*32);
#pragma unroll
        for (int ti = 0; ti < 4; ti++) {
            if (ti >= ntiles) break;
            uint32_t a0,a1,a2,a3;
            ldsm4(a0,a1,a2,a3, aaddr[ti] + aoff);
            mma16(acc[ti][0], a0,a1,a2,a3, b0,b1);
            mma16(acc[ti][1], a0,a1,a2,a3, b2,b3);
            mma16(acc[ti][2], a0,a1,a2,a3, c0,c1);
            mma16(acc[ti][3], a0,a1,a2,a3, c2,c3);
        }
    }
    __syncthreads();

    float* res = (float*)smh;          // 32*401 floats
#pragma unroll
    for (int ti = 0; ti < 4; ti++) {
        if (ti >= ntiles) break;
        int t = wp + 8*ti;
        int p0 = t*16 + gr, p1 = p0 + 8;
#pragma unroll
        for (int nt = 0; nt < 4; nt++) {
            int oc0 = nt*8 + 2*gc;
            res[oc0*401 + p0]     = acc[ti][nt][0];
            res[(oc0+1)*401 + p0] = acc[ti][nt][1];
            res[oc0*401 + p1]     = acc[ti][nt][2];
            res[(oc0+1)*401 + p1] = acc[ti][nt][3];
        }
    }
    __syncthreads();

    for (int item = tid; item < 3200; item += 256) {
        int pos = item >> 5, oc = item & 31;
        int py = pos / 10, px = pos - py*10;
        float bv = cb[oc];
        const __half* xrb = inb + ((size_t)(gi*20 + 2*py)*160 + gj*20 + 2*px)*32 + oc;
        int p = (2*py)*20 + 2*px;
        const float* rr = &res[oc*401];
        float v0 = fmaxf(rr[p]      + bv + __half2float(xrb[0]),        0.f);
        float v1 = fmaxf(rr[p + 1]  + bv + __half2float(xrb[32]),       0.f);
        float v2 = fmaxf(rr[p + 20] + bv + __half2float(xrb[160*32]),   0.f);
        float v3 = fmaxf(rr[p + 21] + bv + __half2float(xrb[160*32+32]),0.f);
        float mx = fmaxf(fmaxf(v0, v1), fmaxf(v2, v3));
        out[((size_t)(b*80 + gi*10 + py)*80 + gj*10 + px)*32 + oc] =
            __float2half_rn(fmaf(mx, s2[oc], t2[oc]));
    }
}

// =====================================================================
// conv2/conv3 (fp16 mma + ldmatrix)
// =====================================================================
template<int CIN, int HIN, int WIN, int HOUT, int WOUT, int OUT_NHWC, int PRELOAD>
__global__ void __launch_bounds__(256) conv_nhwc(
    const __half* __restrict__ in, const __half* __restrict__ wh,
    const float* __restrict__ bias, void* __restrict__ outv)
{
    constexpr int NCH = CIN/8;
    constexpr int WCH = PRELOAD ? NCH : 1;
    extern __shared__ __half smh[];
    __half* xs = smh;                   // 4240
    __half* ws = smh + 4240;            // WCH*16*520
    float* bs = (float*)(ws + WCH*16*C2_KP);

    const int tid = threadIdx.x, lane = tid & 31, wp = tid >> 5;
    const int b = blockIdx.z;
    const int iy0 = blockIdx.y*16, ix0 = blockIdx.x*16;
    const int gr = lane >> 2, gc = lane & 3;

    if (tid < 16) bs[tid] = bias[tid];
    if (PRELOAD) {
        const uint4* src = (const uint4*)wh;
        uint4* dst = (uint4*)ws;
        for (int i = tid; i < WCH*16*C2_KP/8; i += 256) dst[i] = src[i];
    }

    float acc[2][2][4];
#pragma unroll
    for (int m = 0; m < 2; m++)
#pragma unroll
        for (int n = 0; n < 2; n++)
#pragma unroll
            for (int q = 0; q < 4; q++) acc[m][n][q] = 0.f;

    const int arow = lane & 15;
    const int acol = (lane >> 4) * 8;
    const int boc  = (lane & 7) | ((lane >> 4) << 3);
    const int bk   = ((lane >> 3) & 1) * 8;
    uint32_t aaddr[2];
#pragma unroll
    for (int mt = 0; mt < 2; mt++)
        aaddr[mt] = s2u(xs) + (((wp*2 + mt)*23 + arow)*8 + acol)*2;
    const uint32_t baddr_base = s2u(ws) + (boc*C2_KP + bk)*2;

    for (int cc = 0; cc < CIN; cc += 8) {
        __syncthreads();
        for (int i = tid; i < 529; i += 256) {
            int yy = i / 23, xx = i - yy*23;
            int gy = iy0 + yy, gx = ix0 + xx;
            uint4 v = make_uint4(0u,0u,0u,0u);
            if (gy < HIN && gx < WIN)
                v = *(const uint4*)&in[((size_t)(b*HIN + gy)*WIN + gx)*CIN + cc];
            *(uint4*)&xs[i*8] = v;
        }
        if (!PRELOAD) {
            const uint4* src = (const uint4*)(wh + (size_t)(cc >> 3)*16*C2_KP);
            uint4* dst = (uint4*)ws;
            for (int i = tid; i < 16*C2_KP/8; i += 256) dst[i] = src[i];
        }
        __syncthreads();

        const uint32_t baddr = PRELOAD ? baddr_base + (cc >> 3)*16*C2_KP*2
                                       : baddr_base;
        for (int j = 0; j < 32; j++) {
            int kh = j >> 2, kw0 = (j & 3)*2;
            uint32_t aoff = (kh*23 + kw0)*16;
            uint32_t b0,b1,b2,b3;
            ldsm4(b0,b1,b2,b3, baddr + j*32);
#pragma unroll
            for (int mt = 0; mt < 2; mt++) {
                uint32_t a0,a1,a2,a3;
                ldsm4(a0,a1,a2,a3, aaddr[mt] + aoff);
                mma16(acc[mt][0], a0,a1,a2,a3, b0,b1);
                mma16(acc[mt][1], a0,a1,a2,a3, b2,b3);
            }
        }
    }

    if (OUT_NHWC) {
        float b0l = bs[gc*2],     b1l = bs[gc*2+1];
        float b2l = bs[8+gc*2],   b3l = bs[8+gc*2+1];
        __syncthreads();
        __half* osm = smh;
#pragma unroll
        for (int mt = 0; mt < 2; mt++) {
            int p0 = (wp*2 + mt)*16 + gr;
            *(half2*)&osm[p0*24 + gc*2] = __floats2half2_rn(
                fmaxf(acc[mt][0][0] + b0l, 0.f), fmaxf(acc[mt][0][1] + b1l, 0.f));
            *(half2*)&osm[p0*24 + 8 + gc*2] = __floats2half2_rn(
                fmaxf(acc[mt][1][0] + b2l, 0.f), fmaxf(acc[mt][1][1] + b3l, 0.f));
            *(half2*)&osm[(p0+8)*24 + gc*2] = __floats2half2_rn(
                fmaxf(acc[mt][0][2] + b0l, 0.f), fmaxf(acc[mt][0][3] + b1l, 0.f));
            *(half2*)&osm[(p0+8)*24 + 8 + gc*2] = __floats2half2_rn(
                fmaxf(acc[mt][1][2] + b2l, 0.f), fmaxf(acc[mt][1][3] + b3l, 0.f));
        }
        __syncthreads();
        __half* o = (__half*)outv;
        for (int i = tid; i < 512; i += 256) {
            int p = i >> 1, seg = i & 1;
            int py = p >> 4, px = p & 15;
            int yp = iy0 + py, xp = ix0 + px;
            if (yp < HOUT && xp < WOUT) {
                uint4 v = *(uint4*)&osm[p*24 + seg*8];
                *(uint4*)&o[((size_t)(b*HOUT + yp)*WOUT + xp)*16 + seg*8] = v;
            }
        }
    } else {
        float* outp = (float*)outv;
        const size_t cstride = (size_t)HOUT*WOUT;
#pragma unroll
        for (int mt = 0; mt < 2; mt++) {
            int yp = iy0 + wp*2 + mt;
            int xp = ix0 + gr;
            if (yp >= HOUT) continue;
#pragma unroll
            for (int nt = 0; nt < 2; nt++) {
                int oc = nt*8 + gc*2;
                float* o0 = outp + (((size_t)b*16 + oc)*HOUT + yp)*WOUT + xp;
                if (xp < WOUT) {
                    o0[0]       = fmaxf(acc[mt][nt][0] + bs[oc],   0.f);
                    o0[cstride] = fmaxf(acc[mt][nt][1] + bs[oc+1], 0.f);
                }
                if (xp + 8 < WOUT) {
                    o0[8]         = fmaxf(acc[mt][nt][2] + bs[oc],   0.f);
                    o0[cstride+8] = fmaxf(acc[mt][nt][3] + bs[oc+1], 0.f);
                }
            }
        }
    }
}

// =====================================================================
// conv4/conv5 (tf32): NCHW float — unchanged
// =====================================================================
template<int CIN, int KS, int STRIDE, int HIN, int WIN, int HOUT, int WOUT>
__global__ void __launch_bounds__(256) conv_tcS(
    const float* __restrict__ in, const float* __restrict__ w,
    const float* __restrict__ bias, float* __restrict__ out)
{
    constexpr int TIW = 15*STRIDE + KS;
    constexpr int KCH = 8*KS*KS;
    constexpr int KP  = KCH + 4;
    extern __shared__ uint32_t sm_u[];
    uint32_t* xs = sm_u;
    uint32_t* ws = xs + 8*TIW*TIW;
    int* lut = (int*)(ws + 16*KP);
    float* bs = (float*)(lut + KCH);

    const int tid = threadIdx.x, lane = tid & 31, wp = tid >> 5;
    const int b = blockIdx.z;
    const int iy0in = blockIdx.y*16*STRIDE, ix0in = blockIdx.x*16*STRIDE;

    for (int i = tid; i < KCH; i += 256) {
        int cl = i / (KS*KS), r = i - cl*(KS*KS);
        lut[i] = cl*(TIW*TIW) + (r/KS)*TIW + (r%KS);
    }
    if (tid < 16) bs[tid] = bias[tid];

    float acc[2][2][4];
#pragma unroll
    for (int m = 0; m < 2; m++)
#pragma unroll
        for (int n = 0; n < 2; n++)
#pragma unroll
            for (int q = 0; q < 4; q++) acc[m][n][q] = 0.f;

    const int gr = lane >> 2, gc = lane & 3;
    int mb[2];
#pragma unroll
    for (int i = 0; i < 2; i++)
        mb[i] = (STRIDE*(wp*2 + i))*TIW + STRIDE*gr;
    const int a1off = 8*STRIDE;

    for (int cc = 0; cc < CIN; cc += 8) {
        __syncthreads();
        for (int i = tid; i < 8*TIW*TIW; i += 256) {
            int cl = i / (TIW*TIW), r = i - cl*(TIW*TIW);
            int yy = r / TIW, xx = r - yy*TIW;
            int gy = iy0in + yy, gx = ix0in + xx;
            float v = 0.f;
            if (gy < HIN && gx < WIN)
                v = in[(((size_t)b*CIN + cc + cl)*HIN + gy)*WIN + gx];
            xs[i] = f2tf(v);
        }
        for (int i = tid; i < 16*KCH; i += 256) {
            int oc = i / KCH, kl = i - oc*KCH;
            int cl = kl / (KS*KS), kk = kl - cl*(KS*KS);
            ws[oc*KP + kl] = f2tf(w[((size_t)oc*CIN + cc + cl)*(KS*KS) + kk]);
        }
        __syncthreads();

        for (int k0 = 0; k0 < KCH; k0 += 8) {
            int o1 = lut[k0 + gc], o2 = lut[k0 + gc + 4];
            uint32_t bf0[2], bf1[2];
#pragma unroll
            for (int nt = 0; nt < 2; nt++) {
                const uint32_t* wp_ = &ws[(nt*8 + gr)*KP + k0];
                bf0[nt] = wp_[gc]; bf1[nt] = wp_[gc + 4];
            }
#pragma unroll
            for (int mt = 0; mt < 2; mt++) {
                uint32_t a0 = xs[mb[mt] + o1], a1 = xs[mb[mt] + a1off + o1];
                uint32_t a2 = xs[mb[mt] + o2], a3 = xs[mb[mt] + a1off + o2];
#pragma unroll
                for (int nt = 0; nt < 2; nt++)
                    mma8(acc[mt][nt], a0, a1, a2, a3, bf0[nt], bf1[nt]);
            }
        }
    }

    const size_t cstride = (size_t)HOUT*WOUT;
#pragma unroll
    for (int mt = 0; mt < 2; mt++) {
        int yp = blockIdx.y*16 + wp*2 + mt;
        int xp = blockIdx.x*16 + gr;
        if (yp < HOUT) {
#pragma unroll
            for (int nt = 0; nt < 2; nt++) {
                int oc = nt*8 + gc*2;
                float* o0 = out + (((size_t)b*16 + oc)*HOUT + yp)*WOUT + xp;
                if (xp < WOUT) {
                    o0[0]       = fmaxf(acc[mt][nt][0] + bs[oc],   0.f);
                    o0[cstride] = fmaxf(acc[mt][nt][1] + bs[oc+1], 0.f);
                }
                if (xp + 8 < WOUT) {
                    o0[8]         = fmaxf(acc[mt][nt][2] + bs[oc],   0.f);
                    o0[cstride+8] = fmaxf(acc[mt][nt][3] + bs[oc+1], 0.f);
                }
            }
        }
    }
}

// =====================================================================
// fc (tf32)
// =====================================================================
__global__ void __launch_bounds__(256) fc_tc(
    const float* __restrict__ x, const float* __restrict__ w,
    float* __restrict__ part, int N, int K, int klen)
{
    __shared__ uint32_t as[32*68];
    __shared__ uint32_t bsm[128*68];

    const int tid = threadIdx.x, lane = tid & 31, wp = tid >> 5;
    const int n0 = blockIdx.x*128;
    const int kstart = blockIdx.y*klen;
    const int gr = lane >> 2, gc = lane & 3;
    const int nb = wp*16;

    float acc[2][2][4];
#pragma unroll
    for (int m = 0; m < 2; m++)
#pragma unroll
        for (int n = 0; n < 2; n++)
#pragma unroll
            for (int q = 0; q < 4; q++) acc[m][n][q] = 0.f;

    for (int kc = 0; kc < klen; kc += 64) {
        int cl = min(64, klen - kc);
        __syncthreads();
        for (int i = tid; i < 1024; i += 256) {
            int m = i >> 5, k2 = i & 31;
            int k = k2*2;
            float2 v = make_float2(0.f, 0.f);
            if (k < cl)
                v = *(const float2*)&x[(size_t)m*K + kstart + kc + k];
            as[m*68 + k]     = f2tf(v.x);
            as[m*68 + k + 1] = f2tf(v.y);
        }
        for (int i = tid; i < 4096; i += 256) {
            int n = i >> 5, k2 = i & 31;
            int k = k2*2;
            float2 v = make_float2(0.f, 0.f);
            if (k < cl)
                v = *(const float2*)&w[(size_t)(n0 + n)*K + kstart + kc + k];
            bsm[n*68 + k]     = f2tf(v.x);
            bsm[n*68 + k + 1] = f2tf(v.y);
        }
        __syncthreads();

#pragma unroll
        for (int k0 = 0; k0 < 64; k0 += 8) {
            uint32_t a0[2], a1[2], a2[2], a3[2];
#pragma unroll
            for (int mt = 0; mt < 2; mt++) {
                const uint32_t* ap = &as[(mt*16 + gr)*68 + k0];
                a0[mt] = ap[gc];        a2[mt] = ap[gc + 4];
                a1[mt] = ap[8*68 + gc]; a3[mt] = ap[8*68 + gc + 4];
            }
#pragma unroll
            for (int nt = 0; nt < 2; nt++) {
                const uint32_t* bp = &bsm[(nb + nt*8 + gr)*68 + k0];
                uint32_t b0 = bp[gc], b1 = bp[gc + 4];
#pragma unroll
                for (int mt = 0; mt < 2; mt++)
                    mma8(acc[mt][nt], a0[mt], a1[mt], a2[mt], a3[mt], b0, b1);
            }
        }
    }

    float* pr = part + (size_t)blockIdx.y*32*N;
#pragma unroll
    for (int mt = 0; mt < 2; mt++) {
#pragma unroll
        for (int nt = 0; nt < 2; nt++) {
            int n = n0 + nb + nt*8 + 2*gc;
            int m0 = mt*16 + gr;
            *(float2*)&pr[(size_t)m0*N + n]     = make_float2(acc[mt][nt][0], acc[mt][nt][1]);
            *(float2*)&pr[(size_t)(m0+8)*N + n] = make_float2(acc[mt][nt][2], acc[mt][nt][3]);
        }
    }
}

__global__ void fc_reduce(const float* __restrict__ part,
                          const float* __restrict__ bias,
                          float* __restrict__ out, int N, int KT, int do_relu)
{
    int i = blockIdx.x*256 + threadIdx.x;
    if (i >= 32*N) return;
    int n = i % N;
    float s = bias[n];
    for (int kt = 0; kt < KT; kt++) s += part[(size_t)kt*32*N + i];
    out[i] = do_relu ? fmaxf(s, 0.f) : s;
}

__global__ void __launch_bounds__(768) fc3_softmax(
    const float* __restrict__ x, const float* __restrict__ w,
    const float* __restrict__ bias, float* __restrict__ out)
{
    __shared__ float lg[24];
    const int b = blockIdx.x;
    const int tid = threadIdx.x;
    const int wo = tid >> 5, lane = tid & 31;

    const float* xr = x + (size_t)b*2048;
    const float* wr = w + (size_t)wo*2048;
    float s = 0.f;
    for (int k = lane; k < 2048; k += 32) s = fmaf(wr[k], xr[k], s);
#pragma unroll
    for (int off = 16; off; off >>= 1) s += __shfl_xor_sync(0xffffffffu, s, off);
    if (lane == 0) lg[wo] = s + bias[wo];
    __syncthreads();

    if (tid < 24) {
        int a = tid % 12;
        float z0 = lg[a], z1 = lg[12 + a];
        float m = fmaxf(z0, z1);
        float lse = m + logf(expf(z0 - m) + expf(z1 - m));
        out[b*24 + tid] = lg[tid] - lse;
    }
}

// =====================================================================
// launch
// =====================================================================
extern "C" void kernel_launch(void* const* d_in, const int* in_sizes, int n_in,
                              void* d_out, int out_size)
{
    const float* x        = (const float*)d_in[0];
    const float* conv1_w  = (const float*)d_in[1];
    const float* conv1_b  = (const float*)d_in[2];
    const float* rl_gamma = (const float*)d_in[3];
    const float* rl_beta  = (const float*)d_in[4];
    const float* rl_mean  = (const float*)d_in[5];
    const float* rl_var   = (const float*)d_in[6];
    const float* rl_cw    = (const float*)d_in[7];
    const float* rl_cb    = (const float*)d_in[8];
    const float* bn_gamma = (const float*)d_in[9];
    const float* bn_beta  = (const float*)d_in[10];
    const float* bn_mean  = (const float*)d_in[11];
    const float* bn_var   = (const float*)d_in[12];
    const float* conv2_w  = (const float*)d_in[13];
    const float* conv2_b  = (const float*)d_in[14];
    const float* conv3_w  = (const float*)d_in[15];
    const float* conv3_b  = (const float*)d_in[16];
    const float* conv4_w  = (const float*)d_in[17];
    const float* conv4_b  = (const float*)d_in[18];
    const float* conv5_w  = (const float*)d_in[19];
    const float* conv5_b  = (const float*)d_in[20];
    const float* fc1_w    = (const float*)d_in[21];
    const float* fc1_b    = (const float*)d_in[22];
    const float* fc2_w    = (const float*)d_in[23];
    const float* fc2_b    = (const float*)d_in[24];
    const float* fc3_w    = (const float*)d_in[25];
    const float* fc3_b    = (const float*)d_in[26];
    float* out = (float*)d_out;

    __half *xh, *b1h, *b2h, *b3h, *w1h, *w2h, *w3h, *wrh;
    float *b4,*b5,*b6,*pt,*f1,*f2;
    cudaGetSymbolAddress((void**)&xh, g_xh);
    cudaGetSymbolAddress((void**)&b1h, g_buf1h);
    cudaGetSymbolAddress((void**)&b2h, g_buf2h);
    cudaGetSymbolAddress((void**)&b3h, g_buf3h);
    cudaGetSymbolAddress((void**)&b4, g_buf4);
    cudaGetSymbolAddress((void**)&b5, g_buf5);
    cudaGetSymbolAddress((void**)&b6, g_buf6);
    cudaGetSymbolAddress((void**)&pt, g_part);
    cudaGetSymbolAddress((void**)&f1, g_fc1);
    cudaGetSymbolAddress((void**)&f2, g_fc2);
    cudaGetSymbolAddress((void**)&w1h, g_w1h);
    cudaGetSymbolAddress((void**)&w2h, g_w2h);
    cudaGetSymbolAddress((void**)&w3h, g_w3h);
    cudaGetSymbolAddress((void**)&wrh, g_wrh);

    const int c1_smem = (2*C1_XSH + 32*C1_KP)*2 + 32*4;
    cudaFuncSetAttribute(conv1_h,
                         cudaFuncAttributeMaxDynamicSharedMemorySize, c1_smem);
    const int reg_smem = (4*RG_CH + 32*RG_KP)*2;
    cudaFuncSetAttribute(region_h,
                         cudaFuncAttributeMaxDynamicSharedMemorySize, reg_smem);
    const int c2_smem = (4240 + 16*C2_KP)*2 + 16*4;
    cudaFuncSetAttribute((const void*)conv_nhwc<32,80,80,73,73,1,0>,
                         cudaFuncAttributeMaxDynamicSharedMemorySize, c2_smem);
    const int c3_smem = (4240 + 2*16*C2_KP)*2 + 16*4;
    cudaFuncSetAttribute((const void*)conv_nhwc<16,73,73,66,66,0,1>,
                         cudaFuncAttributeMaxDynamicSharedMemorySize, c3_smem);
    const int c4_smem = (8*36*36 + 16*292 + 288 + 16) * 4;
    cudaFuncSetAttribute(conv_tcS<16,6,2,66,66,31,31>,
                         cudaFuncAttributeMaxDynamicSharedMemorySize, c4_smem);
    const int c5_smem = (8*20*20 + 16*204 + 200 + 16) * 4;
    cudaFuncSetAttribute(conv_tcS<16,5,1,31,31,27,27>,
                         cudaFuncAttributeMaxDynamicSharedMemorySize, c5_smem);

    // 0. prep: input + weights
    prep_x<<<(BATCH*170*170 + 255)/256, 256>>>(x, xh);
    prep_w1<<<(32*C1_KP + 255)/256, 256>>>(conv1_w, w1h);
    prep_w2<<<(4*16*C2_KP + 255)/256, 256>>>(conv2_w, w2h, 32);
    prep_w2<<<(2*16*C2_KP + 255)/256, 256>>>(conv3_w, w3h, 16);
    prep_wr<<<(64*32*RG_KP + 255)/256, 256>>>(rl_cw, wrh);

    // 1. conv1 (vectorized staging from NHWC4 half input)
    conv1_h<<<dim3(5,10,BATCH), 256, c1_smem>>>(xh, w1h, conv1_b, b1h);

    // 2. region
    region_h<<<BATCH*64, 256, reg_smem>>>(
        b1h, wrh, rl_gamma, rl_beta, rl_mean, rl_var, rl_cb,
        bn_gamma, bn_beta, bn_mean, bn_var, b2h);

    // 3. conv2
    conv_nhwc<32,80,80,73,73,1,0><<<dim3(5,5,BATCH), 256, c2_smem>>>(
        b2h, w2h, conv2_b, b3h);

    // 4. conv3 (weights preloaded)
    conv_nhwc<16,73,73,66,66,0,1><<<dim3(5,5,BATCH), 256, c3_smem>>>(
        b3h, w3h, conv3_b, b4);

    // 5. conv4
    conv_tcS<16,6,2,66,66,31,31><<<dim3(2,2,BATCH), 256, c4_smem>>>(
        b4, conv4_w, conv4_b, b5);

    // 6. conv5
    conv_tcS<16,5,1,31,31,27,27><<<dim3(2,2,BATCH), 256, c5_smem>>>(
        b5, conv5_w, conv5_b, b6);

    // 7. fc1
    fc_tc<<<dim3(32,24), 256>>>(b6, fc1_w, pt, 4096, 11664, 486);
    fc_reduce<<<512, 256>>>(pt, fc1_b, f1, 4096, 24, 1);

    // 8. fc2
    fc_tc<<<dim3(16,16), 256>>>(f1, fc2_w, pt, 2048, 4096, 256);
    fc_reduce<<<256, 256>>>(pt, fc2_b, f2, 2048, 16, 1);

    // 9. fc3 + log_softmax
    fc3_softmax<<<BATCH, 768>>>(f2, fc3_w, fc3_b, out);
}